// round 9
// baseline (speedup 1.0000x reference)
#include <cuda_runtime.h>
#include <cuda_fp16.h>
#include <math.h>
#include <stdint.h>

// Problem constants
#define BBAT 4
#define LLEN 2048
#define HH   16
#define HID  1024
#define FF   4096
#define ROWS 8192            // B*L
#define NCHK 32              // scan chunks
#define CHL  64              // scan chunk length
#define EPSV 1e-5f

// ------------------- scratch (static device memory; no allocs) ---------------
__device__ float g_a [ROWS*HID];
__device__ float g_b [ROWS*HID];
__device__ float g_d [ROWS*HID];
__device__ float g_h [ROWS*HID];
__device__ float g_ap[ROWS*HID];
__device__ float g_z [ROWS*HID];
__device__ float g_u [ROWS*HID];
__device__ float g_aggA [BBAT*HH*NCHK*64];
__device__ float g_aggH [BBAT*HH*NCHK*64];
__device__ float g_carry[BBAT*HH*NCHK*64];

// fp16 activation buffers
__device__ __half g_e[ROWS*HID];
__device__ __half g_uh[ROWS*HID];
__device__ __half g_m[ROWS*FF];
__device__ __half g_v[ROWS*HID];
// fp16 weight buffers, transposed to [N,K]; lo only where compensated (Wa)
__device__ __half g_wahi[HID*HID], g_walo[HID*HID];
__device__ __half g_wbhi[HID*HID];
__device__ __half g_wdhi[HID*HID];
__device__ __half g_f1hi[FF*HID];
__device__ __half g_f2hi[HID*FF];
__device__ __half g_pjhi[HID*HID];

__device__ __forceinline__ float gelu_exact(float x) {
    return 0.5f * x * (1.0f + erff(x * 0.7071067811865476f));
}
__device__ __forceinline__ uint32_t pack2h(float a, float b) {
    __half2 t = __floats2half2_rn(a, b);
    return *(uint32_t*)&t;
}
__device__ __forceinline__ uint32_t smem_u32(const void* p) {
    uint32_t a;
    asm("{ .reg .u64 t; cvta.to.shared.u64 t, %1; cvt.u32.u64 %0, t; }" : "=r"(a) : "l"(p));
    return a;
}

#define MMA_OP(d, a, b) \
    asm volatile("mma.sync.aligned.m16n8k16.row.col.f32.f16.f16.f32 " \
                 "{%0,%1,%2,%3},{%4,%5,%6,%7},{%8,%9},{%0,%1,%2,%3};" \
                 : "+f"((d)[0]), "+f"((d)[1]), "+f"((d)[2]), "+f"((d)[3]) \
                 : "r"((a)[0]), "r"((a)[1]), "r"((a)[2]), "r"((a)[3]), \
                   "r"((b)[0]), "r"((b)[1]))

#define LDSM4(r, addr) \
    asm volatile("ldmatrix.sync.aligned.m8n8.x4.shared.b16 {%0,%1,%2,%3}, [%4];" \
                 : "=r"((r)[0]), "=r"((r)[1]), "=r"((r)[2]), "=r"((r)[3]) : "r"(addr))

#define CP16(dst, src) \
    asm volatile("cp.async.cg.shared.global [%0], [%1], 16;" :: "r"(dst), "l"(src))

// ------------------- fp16 compensated GEMM -----------------------------------
// C[M,N] = epi(A @ (Bh[+Bl])^T + bias) (+res). A=[M,K] fp16, Bh/Bl=[N,K] fp16.
// Block 128x128x32, 3-stage cp.async pipeline, 8 warps (2m x 4n), 2 CTA/SM.
// COMP=1: two MMAs (hi+lo weights). COMP=0: single MMA (hi only).
// OUT=0: fp32 Cf. OUT=1: fp16 Chf. OUT=2: both.
#define PADB 80
#define A_OFF  0
#define BH_OFF 10240
#define BL_OFF 20480

template<int COMP> struct StageSz { static const int v = COMP ? 30720 : 20480; };

template<int COMP>
__device__ __forceinline__ void issue_stage(
    uint32_t base, int tid, int m0, int n0, int k0, int K,
    const __half* Ag, const __half* Bhg, const __half* Blg)
{
#pragma unroll
    for (int r = 0; r < 2; r++) {
        int id = tid + r * 256;
        int row = id >> 2, ch = id & 3;
        uint32_t d = base + row * PADB + ch * 16;
        size_t ga = (size_t)(m0 + row) * K + k0 + ch * 8;
        size_t gb = (size_t)(n0 + row) * K + k0 + ch * 8;
        CP16(d + A_OFF,  Ag + ga);
        CP16(d + BH_OFF, Bhg + gb);
        if (COMP) CP16(d + BL_OFF, Blg + gb);
    }
    asm volatile("cp.async.commit_group;");
}

template<int EPI, int RES, int OUT, int COMP>
__global__ void __launch_bounds__(256, 2)
hgemm(const __half* __restrict__ Ag,
      const __half* __restrict__ Bhg, const __half* __restrict__ Blg,
      const float* __restrict__ bias, const float* __restrict__ res,
      float* __restrict__ Cf, __half* __restrict__ Chf,
      int M, int N, int K)
{
    const int STG_SZ = StageSz<COMP>::v;
    extern __shared__ __align__(16) char sm[];
    const uint32_t sb = smem_u32(sm);
    const int tid = threadIdx.x;
    const int m0 = blockIdx.y * 128;
    const int n0 = blockIdx.x * 128;
    const int lane = tid & 31;
    const int wid = tid >> 5;
    const int wm = (wid & 1) * 64;
    const int wn = (wid >> 1) * 32;
    const int g = lane >> 2;
    const int t = lane & 3;
    const int q = lane >> 3;
    const int rr8 = lane & 7;

    float acc[4][4][4];
#pragma unroll
    for (int i = 0; i < 4; i++)
#pragma unroll
        for (int j = 0; j < 4; j++)
#pragma unroll
            for (int r = 0; r < 4; r++) acc[i][j][r] = 0.f;

    const int nch = K >> 5;
    issue_stage<COMP>(sb,          tid, m0, n0, 0,  K, Ag, Bhg, Blg);
    issue_stage<COMP>(sb + STG_SZ, tid, m0, n0, 32, K, Ag, Bhg, Blg);

    const uint32_t a_lane = (uint32_t)((wm + ((q & 1) << 3) + rr8) * PADB + ((q >> 1) << 3) * 2);
    const uint32_t b_lane = (uint32_t)((wn + ((q >> 1) << 3) + rr8) * PADB + ((q & 1) << 3) * 2) + BH_OFF;

    int stg = 0;
    for (int c = 0; c < nch; c++) {
        const uint32_t base = sb + stg * STG_SZ;
        if (c + 1 < nch) asm volatile("cp.async.wait_group 1;");
        else             asm volatile("cp.async.wait_group 0;");
        __syncthreads();
        if (c + 2 < nch) {
            int ns = stg + 2; if (ns >= 3) ns -= 3;
            issue_stage<COMP>(sb + ns * STG_SZ, tid, m0, n0, (c + 2) << 5, K, Ag, Bhg, Blg);
        }

#pragma unroll
        for (int ks = 0; ks < 32; ks += 16) {
            uint32_t bh[2][4], bl[2][4];
#pragma unroll
            for (int p = 0; p < 2; p++) {
                uint32_t ad = base + b_lane + (uint32_t)(p * 16 * PADB + ks * 2);
                LDSM4(bh[p], ad);
                if (COMP) LDSM4(bl[p], ad + (BL_OFF - BH_OFF));
            }
#pragma unroll
            for (int mt = 0; mt < 4; mt++) {
                uint32_t ad = base + a_lane + (uint32_t)(mt * 16 * PADB + ks * 2);
                uint32_t ah[4];
                LDSM4(ah, ad);
#pragma unroll
                for (int nt = 0; nt < 4; nt++) {
                    uint32_t* bhp = &bh[nt >> 1][(nt & 1) * 2];
                    MMA_OP(acc[mt][nt], ah, bhp);
                    if (COMP) {
                        uint32_t* blp = &bl[nt >> 1][(nt & 1) * 2];
                        MMA_OP(acc[mt][nt], ah, blp);
                    }
                }
            }
        }
        stg++; if (stg >= 3) stg = 0;
    }

    // ---- epilogue ----
#pragma unroll
    for (int mt = 0; mt < 4; mt++) {
#pragma unroll
        for (int nt = 0; nt < 4; nt++) {
            int row0 = m0 + wm + mt * 16 + g;
            int col = n0 + wn + nt * 8 + t * 2;
            float b0 = __ldg(bias + col), b1 = __ldg(bias + col + 1);
#pragma unroll
            for (int half = 0; half < 2; half++) {
                int rw = row0 + half * 8;
                float v0 = acc[mt][nt][half * 2 + 0] + b0;
                float v1 = acc[mt][nt][half * 2 + 1] + b1;
                if (EPI == 1) { v0 = tanhf(v0); v1 = tanhf(v1); }
                else if (EPI == 2) { v0 = gelu_exact(v0); v1 = gelu_exact(v1); }
                if (RES) {
                    const float2 rv = *(const float2*)(res + (size_t)rw * N + col);
                    v0 += rv.x; v1 += rv.y;
                }
                if (OUT == 0 || OUT == 2) {
                    float2 o; o.x = v0; o.y = v1;
                    *(float2*)(Cf + (size_t)rw * N + col) = o;
                }
                if (OUT == 1 || OUT == 2) {
                    *(uint32_t*)(Chf + (size_t)rw * N + col) = pack2h(v0, v1);
                }
            }
        }
    }
}

// ------------------- conversion kernels --------------------------------------
__global__ void tohalf_k(const float* __restrict__ in, __half* __restrict__ o, int nvec)
{
    int i = blockIdx.x * blockDim.x + threadIdx.x;
    if (i >= nvec) return;
    float4 v = ((const float4*)in)[i];
    uint2 p = make_uint2(pack2h(v.x, v.y), pack2h(v.z, v.w));
    ((uint2*)o)[i] = p;
}

// transpose+split: out[n][k] = in(k,n); BLAY=0: in[K,N] row-major; BLAY=1: in=[H,K,64]
template<int BLAY>
__global__ void convT_k(const float* __restrict__ in, __half* __restrict__ hi,
                        __half* __restrict__ lo, int K, int N)
{
    __shared__ float t[32][33];
    int k0 = blockIdx.x * 32, n0 = blockIdx.y * 32;
    int tx = threadIdx.x, ty = threadIdx.y;
    for (int r = ty; r < 32; r += 8) {
        int k = k0 + r, n = n0 + tx;
        size_t idx;
        if (BLAY) idx = ((size_t)(n >> 6) * K + k) * 64 + (n & 63);
        else      idx = (size_t)k * N + n;
        t[r][tx] = in[idx];
    }
    __syncthreads();
    for (int r = ty; r < 32; r += 8) {
        int n = n0 + r, k = k0 + tx;
        float v = t[tx][r];
        __half h = __float2half_rn(v);
        hi[(size_t)n * K + k] = h;
        if (lo) lo[(size_t)n * K + k] = __float2half_rn(v - __half2float(h));
    }
}

// ------------------- scan kernels -------------------------------------------
__global__ void scan1_k(const float* __restrict__ a, const float* __restrict__ b,
                        float* __restrict__ hout, float* __restrict__ apre,
                        float* __restrict__ aggA, float* __restrict__ aggH)
{
    int blk = blockIdx.x;
    int c = blk & (NCHK - 1);
    int bh = blk >> 5;
    int hh = bh & (HH - 1);
    int bb = bh >> 4;
    int d = threadIdx.x;
    int l0 = c * CHL;
    float A = 1.f, Hl = 0.f;
#pragma unroll 4
    for (int t = 0; t < CHL; t++) {
        size_t idx = (size_t)(bb * LLEN + l0 + t) * HID + hh * 64 + d;
        float av = a[idx], bv = b[idx];
        Hl = fmaf(av, Hl, bv);
        A *= av;
        hout[idx] = Hl;
        apre[idx] = A;
    }
    int ai = (bh * NCHK + c) * 64 + d;
    aggA[ai] = A;
    aggH[ai] = Hl;
}

__global__ void scan2_k(const float* __restrict__ aggA, const float* __restrict__ aggH,
                        float* __restrict__ carry)
{
    int bh = blockIdx.x;
    int d = threadIdx.x;
    float c = 0.f;
#pragma unroll
    for (int ch = 0; ch < NCHK; ch++) {
        int ai = (bh * NCHK + ch) * 64 + d;
        carry[ai] = c;
        c = fmaf(aggA[ai], c, aggH[ai]);
    }
}

// ------------------- per-head GEMM with fused scan fixup ----------------------
// z = ((h + carry*ap) @ WC[h] + bC[h]) * d
__global__ void __launch_bounds__(256)
head_k(const float* __restrict__ hmat, const float* __restrict__ apre,
       const float* __restrict__ carry,
       const float* __restrict__ WC, const float* __restrict__ bC,
       const float* __restrict__ dg, float* __restrict__ z)
{
    __shared__ float Ws[64][65];
    __shared__ float Hs[64][129];
    int hh = blockIdx.y;
    int r0 = blockIdx.x * 128;
    int tid = threadIdx.x;

    const float* wp = WC + (size_t)hh * 64 * 64;
    for (int id = tid; id < 1024; id += 256) {
        int k = id >> 4; int f = (id & 15) * 4;
        float4 v = *(const float4*)(wp + k * 64 + f);
        Ws[k][f] = v.x; Ws[k][f+1] = v.y; Ws[k][f+2] = v.z; Ws[k][f+3] = v.w;
    }
    for (int id = tid; id < 2048; id += 256) {
        int row = id >> 4; int d4 = (id & 15) * 4;
        int rg = r0 + row;
        size_t gi = (size_t)rg * HID + hh * 64 + d4;
        float4 v  = *(const float4*)(hmat + gi);
        float4 ap = *(const float4*)(apre + gi);
        int bb = rg >> 11, l = rg & (LLEN - 1), cc = l >> 6;
        int ai = (((bb * HH + hh) * NCHK) + cc) * 64 + d4;
        float4 cr = *(const float4*)(carry + ai);
        Hs[d4][row]   = fmaf(cr.x, ap.x, v.x);
        Hs[d4+1][row] = fmaf(cr.y, ap.y, v.y);
        Hs[d4+2][row] = fmaf(cr.z, ap.z, v.z);
        Hs[d4+3][row] = fmaf(cr.w, ap.w, v.w);
    }
    __syncthreads();

    int tx = tid & 15, ty = tid >> 4;
    float acc[8][4];
#pragma unroll
    for (int i = 0; i < 8; i++)
#pragma unroll
        for (int j = 0; j < 4; j++) acc[i][j] = 0.f;

#pragma unroll 8
    for (int k = 0; k < 64; k++) {
        float ar[8], br[4];
#pragma unroll
        for (int i = 0; i < 8; i++) ar[i] = Hs[k][ty * 8 + i];
#pragma unroll
        for (int j = 0; j < 4; j++) br[j] = Ws[k][tx * 4 + j];
#pragma unroll
        for (int i = 0; i < 8; i++)
#pragma unroll
            for (int j = 0; j < 4; j++)
                acc[i][j] = fmaf(ar[i], br[j], acc[i][j]);
    }
#pragma unroll
    for (int i = 0; i < 8; i++) {
        int row = r0 + ty * 8 + i;
#pragma unroll
        for (int j = 0; j < 4; j++) {
            int f = tx * 4 + j;
            size_t idx = (size_t)row * HID + hh * 64 + f;
            z[idx] = (acc[i][j] + bC[hh * 64 + f]) * dg[idx];
        }
    }
}

// ------------------- layernorm: u = z + LN(z), emits fp32 + fp16 -------------
__device__ __forceinline__ float warp_sum(float v) {
#pragma unroll
    for (int o = 16; o > 0; o >>= 1) v += __shfl_xor_sync(0xffffffffu, v, o);
    return v;
}

__global__ void __launch_bounds__(256)
ln2_k(const float* __restrict__ z, const float* __restrict__ g,
      const float* __restrict__ be, float* __restrict__ u, __half* __restrict__ uh)
{
    __shared__ float red[8];
    int row = blockIdx.x;
    int tid = threadIdx.x;
    const float* zr = z + (size_t)row * HID;
    float4 v = *(const float4*)(zr + tid * 4);

    float s = v.x + v.y + v.z + v.w;
    s = warp_sum(s);
    if ((tid & 31) == 0) red[tid >> 5] = s;
    __syncthreads();
    float tot = 0.f;
#pragma unroll
    for (int i = 0; i < 8; i++) tot += red[i];
    float mu = tot * (1.0f / HID);
    __syncthreads();

    float dx0 = v.x - mu, dx1 = v.y - mu, dx2 = v.z - mu, dx3 = v.w - mu;
    float ss = dx0*dx0 + dx1*dx1 + dx2*dx2 + dx3*dx3;
    ss = warp_sum(ss);
    if ((tid & 31) == 0) red[tid >> 5] = ss;
    __syncthreads();
    float tot2 = 0.f;
#pragma unroll
    for (int i = 0; i < 8; i++) tot2 += red[i];
    float rstd = rsqrtf(tot2 * (1.0f / HID) + EPSV);

    float4 gv = *(const float4*)(g + tid * 4);
    float4 bv = *(const float4*)(be + tid * 4);
    float4 o;
    o.x = v.x + dx0 * rstd * gv.x + bv.x;
    o.y = v.y + dx1 * rstd * gv.y + bv.y;
    o.z = v.z + dx2 * rstd * gv.z + bv.z;
    o.w = v.w + dx3 * rstd * gv.w + bv.w;
    *(float4*)(u + (size_t)row * HID + tid * 4) = o;
    *(uint2*)(uh + (size_t)row * HID + tid * 4) =
        make_uint2(pack2h(o.x, o.y), pack2h(o.z, o.w));
}

// ------------------- launch -------------------------------------------------
extern "C" void kernel_launch(void* const* d_in, const int* in_sizes, int n_in,
                              void* d_out, int out_size)
{
    const float* emb    = (const float*)d_in[0];
    const float* Wa     = (const float*)d_in[1];
    const float* ba     = (const float*)d_in[2];
    const float* Wb     = (const float*)d_in[3];
    const float* bb     = (const float*)d_in[4];
    const float* WD     = (const float*)d_in[5];
    const float* bD     = (const float*)d_in[6];
    const float* WC     = (const float*)d_in[7];
    const float* bC     = (const float*)d_in[8];
    const float* ffn1_w = (const float*)d_in[9];
    const float* ffn1_b = (const float*)d_in[10];
    const float* ffn2_w = (const float*)d_in[11];
    const float* ffn2_b = (const float*)d_in[12];
    const float* proj_w = (const float*)d_in[13];
    const float* proj_b = (const float*)d_in[14];
    const float* ln_g   = (const float*)d_in[15];
    const float* ln_b   = (const float*)d_in[16];
    float* out = (float*)d_out;

    float *pa, *pb, *pd, *ph, *pap, *pz, *pu, *paggA, *paggH, *pcarry;
    cudaGetSymbolAddress((void**)&pa, g_a);       cudaGetSymbolAddress((void**)&pb, g_b);
    cudaGetSymbolAddress((void**)&pd, g_d);       cudaGetSymbolAddress((void**)&ph, g_h);
    cudaGetSymbolAddress((void**)&pap, g_ap);     cudaGetSymbolAddress((void**)&pz, g_z);
    cudaGetSymbolAddress((void**)&pu, g_u);
    cudaGetSymbolAddress((void**)&paggA, g_aggA); cudaGetSymbolAddress((void**)&paggH, g_aggH);
    cudaGetSymbolAddress((void**)&pcarry, g_carry);

    __half *pe, *puh, *pm, *pv;
    __half *wahi, *walo, *wbhi, *wdhi, *f1hi, *f2hi, *pjhi;
    cudaGetSymbolAddress((void**)&pe, g_e);      cudaGetSymbolAddress((void**)&puh, g_uh);
    cudaGetSymbolAddress((void**)&pm, g_m);      cudaGetSymbolAddress((void**)&pv, g_v);
    cudaGetSymbolAddress((void**)&wahi, g_wahi); cudaGetSymbolAddress((void**)&walo, g_walo);
    cudaGetSymbolAddress((void**)&wbhi, g_wbhi);
    cudaGetSymbolAddress((void**)&wdhi, g_wdhi);
    cudaGetSymbolAddress((void**)&f1hi, g_f1hi); cudaGetSymbolAddress((void**)&f2hi, g_f2hi);
    cudaGetSymbolAddress((void**)&pjhi, g_pjhi);

    const int SM_C1 = 3 * StageSz<1>::v;   // 92160
    const int SM_C0 = 3 * StageSz<0>::v;   // 61440
    cudaFuncSetAttribute((const void*)hgemm<1,0,0,1>, cudaFuncAttributeMaxDynamicSharedMemorySize, SM_C1);
    cudaFuncSetAttribute((const void*)hgemm<0,0,0,0>, cudaFuncAttributeMaxDynamicSharedMemorySize, SM_C0);
    cudaFuncSetAttribute((const void*)hgemm<2,0,1,0>, cudaFuncAttributeMaxDynamicSharedMemorySize, SM_C0);
    cudaFuncSetAttribute((const void*)hgemm<0,1,1,0>, cudaFuncAttributeMaxDynamicSharedMemorySize, SM_C0);

    // ---- operand preparation ----
    tohalf_k<<<(ROWS * HID / 4 + 255) / 256, 256>>>(emb, pe, ROWS * HID / 4);
    convT_k<1><<<dim3(HID/32, HID/32), dim3(32,8)>>>(Wa, wahi, walo, HID, HID);
    convT_k<1><<<dim3(HID/32, HID/32), dim3(32,8)>>>(Wb, wbhi, nullptr, HID, HID);
    convT_k<1><<<dim3(HID/32, HID/32), dim3(32,8)>>>(WD, wdhi, nullptr, HID, HID);
    convT_k<0><<<dim3(HID/32, FF/32),  dim3(32,8)>>>(ffn1_w, f1hi, nullptr, HID, FF);
    convT_k<0><<<dim3(FF/32,  HID/32), dim3(32,8)>>>(ffn2_w, f2hi, nullptr, FF, HID);
    convT_k<0><<<dim3(HID/32, HID/32), dim3(32,8)>>>(proj_w, pjhi, nullptr, HID, HID);

    dim3 gH(HID / 128, ROWS / 128);   // (8, 64)
    dim3 gF(FF / 128,  ROWS / 128);   // (32, 64)

    // a = tanh(emb@Wa+ba)  (compensated — feeds the recurrence)
    hgemm<1,0,0,1><<<gH, 256, SM_C1>>>(pe, wahi, walo, ba, nullptr, pa, nullptr, ROWS, HID, HID);
    // b = emb@Wb+bb, d = emb@WD+bD  (uncompensated)
    hgemm<0,0,0,0><<<gH, 256, SM_C0>>>(pe, wbhi, nullptr, bb, nullptr, pb, nullptr, ROWS, HID, HID);
    hgemm<0,0,0,0><<<gH, 256, SM_C0>>>(pe, wdhi, nullptr, bD, nullptr, pd, nullptr, ROWS, HID, HID);

    // affine scan (chunk-local + cross-chunk carries; fixup fused into head_k)
    scan1_k<<<BBAT * HH * NCHK, 64>>>(pa, pb, ph, pap, paggA, paggH);
    scan2_k<<<BBAT * HH, 64>>>(paggA, paggH, pcarry);

    // z = ((h + carry*ap) @ WC + bC) * d
    head_k<<<dim3(ROWS / 128, HH), 256>>>(ph, pap, pcarry, WC, bC, pd, pz);

    // u = z + LN(z); emit u fp32 + fp16
    ln2_k<<<ROWS, 256>>>(pz, ln_g, ln_b, pu, puh);

    // mid = gelu(u@W1 + b1) -> fp16  (uncompensated)
    hgemm<2,0,1,0><<<gF, 256, SM_C0>>>(puh, f1hi, nullptr, ffn1_b, nullptr, nullptr, pm, ROWS, FF, HID);
    // v = mid@W2 + b2 + u -> fp16  (uncompensated)
    hgemm<0,1,1,0><<<gH, 256, SM_C0>>>(pm, f2hi, nullptr, ffn2_b, pu, nullptr, pv, ROWS, HID, FF);
    // out = v@proj + proj_b  (uncompensated)
    hgemm<0,0,0,0><<<gH, 256, SM_C0>>>(pv, pjhi, nullptr, proj_b, nullptr, out, nullptr, ROWS, HID, HID);
}

// round 10
// speedup vs baseline: 1.3847x; 1.3847x over previous
#include <cuda_runtime.h>
#include <cuda_fp16.h>
#include <math.h>
#include <stdint.h>

// Problem constants
#define BBAT 4
#define LLEN 2048
#define HH   16
#define HID  1024
#define FF   4096
#define ROWS 8192            // B*L
#define NCHK 32              // scan chunks
#define CHL  64              // scan chunk length
#define EPSV 1e-5f

// ------------------- scratch (static device memory; no allocs) ---------------
__device__ float g_a [ROWS*HID];
__device__ float g_b [ROWS*HID];
__device__ float g_d [ROWS*HID];
__device__ float g_h [ROWS*HID];
__device__ float g_ap[ROWS*HID];
__device__ float g_z [ROWS*HID];
__device__ float g_u [ROWS*HID];
__device__ float g_aggA [BBAT*HH*NCHK*64];
__device__ float g_aggH [BBAT*HH*NCHK*64];
__device__ float g_carry[BBAT*HH*NCHK*64];
__device__ float g_bcat[3*HID];

// fp16 activation buffers
__device__ __half g_e[ROWS*HID];
__device__ __half g_uh[ROWS*HID];
__device__ __half g_m[ROWS*FF];
__device__ __half g_v[ROWS*HID];
// fp16 weight buffers, transposed to [N,K]
__device__ __half g_wabdhi[3*HID*HID], g_wabdlo[3*HID*HID];  // Wa|Wb|WD stacked
__device__ __half g_f1hi[FF*HID];
__device__ __half g_f2hi[HID*FF];
__device__ __half g_pjhi[HID*HID], g_pjlo[HID*HID];

__device__ __forceinline__ float gelu_exact(float x) {
    return 0.5f * x * (1.0f + erff(x * 0.7071067811865476f));
}
__device__ __forceinline__ uint32_t pack2h(float a, float b) {
    __half2 t = __floats2half2_rn(a, b);
    return *(uint32_t*)&t;
}
__device__ __forceinline__ uint32_t smem_u32(const void* p) {
    uint32_t a;
    asm("{ .reg .u64 t; cvta.to.shared.u64 t, %1; cvt.u32.u64 %0, t; }" : "=r"(a) : "l"(p));
    return a;
}

#define MMA_OP(d, a, b) \
    asm volatile("mma.sync.aligned.m16n8k16.row.col.f32.f16.f16.f32 " \
                 "{%0,%1,%2,%3},{%4,%5,%6,%7},{%8,%9},{%0,%1,%2,%3};" \
                 : "+f"((d)[0]), "+f"((d)[1]), "+f"((d)[2]), "+f"((d)[3]) \
                 : "r"((a)[0]), "r"((a)[1]), "r"((a)[2]), "r"((a)[3]), \
                   "r"((b)[0]), "r"((b)[1]))

#define LDSM4(r, addr) \
    asm volatile("ldmatrix.sync.aligned.m8n8.x4.shared.b16 {%0,%1,%2,%3}, [%4];" \
                 : "=r"((r)[0]), "=r"((r)[1]), "=r"((r)[2]), "=r"((r)[3]) : "r"(addr))

#define CP16(dst, src) \
    asm volatile("cp.async.cg.shared.global [%0], [%1], 16;" :: "r"(dst), "l"(src))

// ------------------- fp16 compensated GEMM -----------------------------------
// C[M,N] = epi(A @ (Bh[+Bl])^T + bias) (+res). A=[M,K] fp16, Bh/Bl=[N,K] fp16.
// Block 128x128x32, 3-stage cp.async pipeline, 8 warps (2m x 4n), 2 CTA/SM.
// COMP=1: two MMAs (hi+lo weights). COMP=0: single MMA (hi only).
// EPI: 0 none, 1 tanh, 2 gelu, 3 = fused a/b/d epilogue (column-sectioned,
//      tanh on section 0, outputs to Cf/Cf2/Cf3 each [M,HID] fp32).
// OUT=0: fp32 Cf. OUT=1: fp16 Chf. OUT=2: both.
#define PADB 80
#define A_OFF  0
#define BH_OFF 10240
#define BL_OFF 20480

template<int COMP> struct StageSz { static const int v = COMP ? 30720 : 20480; };

template<int COMP>
__device__ __forceinline__ void issue_stage(
    uint32_t base, int tid, int m0, int n0, int k0, int K,
    const __half* Ag, const __half* Bhg, const __half* Blg)
{
#pragma unroll
    for (int r = 0; r < 2; r++) {
        int id = tid + r * 256;
        int row = id >> 2, ch = id & 3;
        uint32_t d = base + row * PADB + ch * 16;
        size_t ga = (size_t)(m0 + row) * K + k0 + ch * 8;
        size_t gb = (size_t)(n0 + row) * K + k0 + ch * 8;
        CP16(d + A_OFF,  Ag + ga);
        CP16(d + BH_OFF, Bhg + gb);
        if (COMP) CP16(d + BL_OFF, Blg + gb);
    }
    asm volatile("cp.async.commit_group;");
}

template<int EPI, int RES, int OUT, int COMP>
__global__ void __launch_bounds__(256, 2)
hgemm(const __half* __restrict__ Ag,
      const __half* __restrict__ Bhg, const __half* __restrict__ Blg,
      const float* __restrict__ bias, const float* __restrict__ res,
      float* __restrict__ Cf, __half* __restrict__ Chf,
      float* __restrict__ Cf2, float* __restrict__ Cf3,
      int M, int N, int K)
{
    const int STG_SZ = StageSz<COMP>::v;
    extern __shared__ __align__(16) char sm[];
    const uint32_t sb = smem_u32(sm);
    const int tid = threadIdx.x;
    const int m0 = blockIdx.y * 128;
    const int n0 = blockIdx.x * 128;
    const int lane = tid & 31;
    const int wid = tid >> 5;
    const int wm = (wid & 1) * 64;
    const int wn = (wid >> 1) * 32;
    const int g = lane >> 2;
    const int t = lane & 3;
    const int q = lane >> 3;
    const int rr8 = lane & 7;

    float acc[4][4][4];
#pragma unroll
    for (int i = 0; i < 4; i++)
#pragma unroll
        for (int j = 0; j < 4; j++)
#pragma unroll
            for (int r = 0; r < 4; r++) acc[i][j][r] = 0.f;

    const int nch = K >> 5;
    issue_stage<COMP>(sb,          tid, m0, n0, 0,  K, Ag, Bhg, Blg);
    issue_stage<COMP>(sb + STG_SZ, tid, m0, n0, 32, K, Ag, Bhg, Blg);

    const uint32_t a_lane = (uint32_t)((wm + ((q & 1) << 3) + rr8) * PADB + ((q >> 1) << 3) * 2);
    const uint32_t b_lane = (uint32_t)((wn + ((q >> 1) << 3) + rr8) * PADB + ((q & 1) << 3) * 2) + BH_OFF;

    int stg = 0;
    for (int c = 0; c < nch; c++) {
        const uint32_t base = sb + stg * STG_SZ;
        if (c + 1 < nch) asm volatile("cp.async.wait_group 1;");
        else             asm volatile("cp.async.wait_group 0;");
        __syncthreads();
        if (c + 2 < nch) {
            int ns = stg + 2; if (ns >= 3) ns -= 3;
            issue_stage<COMP>(sb + ns * STG_SZ, tid, m0, n0, (c + 2) << 5, K, Ag, Bhg, Blg);
        }

#pragma unroll
        for (int ks = 0; ks < 32; ks += 16) {
            uint32_t bh[2][4], bl[2][4];
#pragma unroll
            for (int p = 0; p < 2; p++) {
                uint32_t ad = base + b_lane + (uint32_t)(p * 16 * PADB + ks * 2);
                LDSM4(bh[p], ad);
                if (COMP) LDSM4(bl[p], ad + (BL_OFF - BH_OFF));
            }
#pragma unroll
            for (int mt = 0; mt < 4; mt++) {
                uint32_t ad = base + a_lane + (uint32_t)(mt * 16 * PADB + ks * 2);
                uint32_t ah[4];
                LDSM4(ah, ad);
#pragma unroll
                for (int nt = 0; nt < 4; nt++) {
                    uint32_t* bhp = &bh[nt >> 1][(nt & 1) * 2];
                    MMA_OP(acc[mt][nt], ah, bhp);
                    if (COMP) {
                        uint32_t* blp = &bl[nt >> 1][(nt & 1) * 2];
                        MMA_OP(acc[mt][nt], ah, blp);
                    }
                }
            }
        }
        stg++; if (stg >= 3) stg = 0;
    }

    // ---- epilogue ----
#pragma unroll
    for (int mt = 0; mt < 4; mt++) {
#pragma unroll
        for (int nt = 0; nt < 4; nt++) {
            int row0 = m0 + wm + mt * 16 + g;
            int col = n0 + wn + nt * 8 + t * 2;
            float b0 = __ldg(bias + col), b1 = __ldg(bias + col + 1);
#pragma unroll
            for (int half = 0; half < 2; half++) {
                int rw = row0 + half * 8;
                float v0 = acc[mt][nt][half * 2 + 0] + b0;
                float v1 = acc[mt][nt][half * 2 + 1] + b1;
                if (EPI == 3) {
                    // fused a/b/d: section by column, tanh only on section 0
                    int sec = col >> 10;
                    int lc = col & 1023;
                    if (sec == 0) { v0 = tanhf(v0); v1 = tanhf(v1); }
                    float* dst = (sec == 0) ? Cf : ((sec == 1) ? Cf2 : Cf3);
                    float2 o; o.x = v0; o.y = v1;
                    *(float2*)(dst + (size_t)rw * HID + lc) = o;
                } else {
                    if (EPI == 1) { v0 = tanhf(v0); v1 = tanhf(v1); }
                    else if (EPI == 2) { v0 = gelu_exact(v0); v1 = gelu_exact(v1); }
                    if (RES) {
                        const float2 rv = *(const float2*)(res + (size_t)rw * N + col);
                        v0 += rv.x; v1 += rv.y;
                    }
                    if (OUT == 0 || OUT == 2) {
                        float2 o; o.x = v0; o.y = v1;
                        *(float2*)(Cf + (size_t)rw * N + col) = o;
                    }
                    if (OUT == 1 || OUT == 2) {
                        *(uint32_t*)(Chf + (size_t)rw * N + col) = pack2h(v0, v1);
                    }
                }
            }
        }
    }
}

// ------------------- conversion kernels --------------------------------------
__global__ void tohalf_k(const float* __restrict__ in, __half* __restrict__ o, int nvec)
{
    int i = blockIdx.x * blockDim.x + threadIdx.x;
    if (i >= nvec) return;
    float4 v = ((const float4*)in)[i];
    uint2 p = make_uint2(pack2h(v.x, v.y), pack2h(v.z, v.w));
    ((uint2*)o)[i] = p;
}

// transpose+split for the 3 stacked [H,K,64] weights -> [3*HID, K] hi/lo
__global__ void convT3_k(const float* __restrict__ w0, const float* __restrict__ w1,
                         const float* __restrict__ w2,
                         __half* __restrict__ hi, __half* __restrict__ lo)
{
    __shared__ float t[32][33];
    const float* in = (blockIdx.z == 0) ? w0 : (blockIdx.z == 1) ? w1 : w2;
    __half* hip = hi + (size_t)blockIdx.z * HID * HID;
    __half* lop = lo + (size_t)blockIdx.z * HID * HID;
    int k0 = blockIdx.x * 32, n0 = blockIdx.y * 32;
    int tx = threadIdx.x, ty = threadIdx.y;
    for (int r = ty; r < 32; r += 8) {
        int k = k0 + r, n = n0 + tx;
        t[r][tx] = in[((size_t)(n >> 6) * HID + k) * 64 + (n & 63)];
    }
    __syncthreads();
    for (int r = ty; r < 32; r += 8) {
        int n = n0 + r, k = k0 + tx;
        float v = t[tx][r];
        __half h = __float2half_rn(v);
        hip[(size_t)n * HID + k] = h;
        lop[(size_t)n * HID + k] = __float2half_rn(v - __half2float(h));
    }
}

__global__ void bias3_k(const float* __restrict__ b0, const float* __restrict__ b1,
                        const float* __restrict__ b2, float* __restrict__ o)
{
    int i = blockIdx.x * blockDim.x + threadIdx.x;
    if (i >= 3 * HID) return;
    o[i] = (i < HID) ? b0[i] : (i < 2 * HID) ? b1[i - HID] : b2[i - 2 * HID];
}

// transpose+split: out[n][k] = in(k,n); in [K,N] row-major
__global__ void convT_k(const float* __restrict__ in, __half* __restrict__ hi,
                        __half* __restrict__ lo, int K, int N)
{
    __shared__ float t[32][33];
    int k0 = blockIdx.x * 32, n0 = blockIdx.y * 32;
    int tx = threadIdx.x, ty = threadIdx.y;
    for (int r = ty; r < 32; r += 8) {
        int k = k0 + r, n = n0 + tx;
        t[r][tx] = in[(size_t)k * N + n];
    }
    __syncthreads();
    for (int r = ty; r < 32; r += 8) {
        int n = n0 + r, k = k0 + tx;
        float v = t[tx][r];
        __half h = __float2half_rn(v);
        hi[(size_t)n * K + k] = h;
        if (lo) lo[(size_t)n * K + k] = __float2half_rn(v - __half2float(h));
    }
}

// ------------------- scan kernels -------------------------------------------
__global__ void scan1_k(const float* __restrict__ a, const float* __restrict__ b,
                        float* __restrict__ hout, float* __restrict__ apre,
                        float* __restrict__ aggA, float* __restrict__ aggH)
{
    int blk = blockIdx.x;
    int c = blk & (NCHK - 1);
    int bh = blk >> 5;
    int hh = bh & (HH - 1);
    int bb = bh >> 4;
    int d = threadIdx.x;
    int l0 = c * CHL;
    float A = 1.f, Hl = 0.f;
#pragma unroll 4
    for (int t = 0; t < CHL; t++) {
        size_t idx = (size_t)(bb * LLEN + l0 + t) * HID + hh * 64 + d;
        float av = a[idx], bv = b[idx];
        Hl = fmaf(av, Hl, bv);
        A *= av;
        hout[idx] = Hl;
        apre[idx] = A;
    }
    int ai = (bh * NCHK + c) * 64 + d;
    aggA[ai] = A;
    aggH[ai] = Hl;
}

__global__ void scan2_k(const float* __restrict__ aggA, const float* __restrict__ aggH,
                        float* __restrict__ carry)
{
    int bh = blockIdx.x;
    int d = threadIdx.x;
    float c = 0.f;
#pragma unroll
    for (int ch = 0; ch < NCHK; ch++) {
        int ai = (bh * NCHK + ch) * 64 + d;
        carry[ai] = c;
        c = fmaf(aggA[ai], c, aggH[ai]);
    }
}

// ------------------- per-head GEMM with fused scan fixup ----------------------
// z = ((h + carry*ap) @ WC[h] + bC[h]) * d
__global__ void __launch_bounds__(256)
head_k(const float* __restrict__ hmat, const float* __restrict__ apre,
       const float* __restrict__ carry,
       const float* __restrict__ WC, const float* __restrict__ bC,
       const float* __restrict__ dg, float* __restrict__ z)
{
    __shared__ float Ws[64][65];
    __shared__ float Hs[64][129];
    int hh = blockIdx.y;
    int r0 = blockIdx.x * 128;
    int tid = threadIdx.x;

    const float* wp = WC + (size_t)hh * 64 * 64;
    for (int id = tid; id < 1024; id += 256) {
        int k = id >> 4; int f = (id & 15) * 4;
        float4 v = *(const float4*)(wp + k * 64 + f);
        Ws[k][f] = v.x; Ws[k][f+1] = v.y; Ws[k][f+2] = v.z; Ws[k][f+3] = v.w;
    }
    for (int id = tid; id < 2048; id += 256) {
        int row = id >> 4; int d4 = (id & 15) * 4;
        int rg = r0 + row;
        size_t gi = (size_t)rg * HID + hh * 64 + d4;
        float4 v  = *(const float4*)(hmat + gi);
        float4 ap = *(const float4*)(apre + gi);
        int bb = rg >> 11, l = rg & (LLEN - 1), cc = l >> 6;
        int ai = (((bb * HH + hh) * NCHK) + cc) * 64 + d4;
        float4 cr = *(const float4*)(carry + ai);
        Hs[d4][row]   = fmaf(cr.x, ap.x, v.x);
        Hs[d4+1][row] = fmaf(cr.y, ap.y, v.y);
        Hs[d4+2][row] = fmaf(cr.z, ap.z, v.z);
        Hs[d4+3][row] = fmaf(cr.w, ap.w, v.w);
    }
    __syncthreads();

    int tx = tid & 15, ty = tid >> 4;
    float acc[8][4];
#pragma unroll
    for (int i = 0; i < 8; i++)
#pragma unroll
        for (int j = 0; j < 4; j++) acc[i][j] = 0.f;

#pragma unroll 8
    for (int k = 0; k < 64; k++) {
        float ar[8], br[4];
#pragma unroll
        for (int i = 0; i < 8; i++) ar[i] = Hs[k][ty * 8 + i];
#pragma unroll
        for (int j = 0; j < 4; j++) br[j] = Ws[k][tx * 4 + j];
#pragma unroll
        for (int i = 0; i < 8; i++)
#pragma unroll
            for (int j = 0; j < 4; j++)
                acc[i][j] = fmaf(ar[i], br[j], acc[i][j]);
    }
#pragma unroll
    for (int i = 0; i < 8; i++) {
        int row = r0 + ty * 8 + i;
#pragma unroll
        for (int j = 0; j < 4; j++) {
            int f = tx * 4 + j;
            size_t idx = (size_t)row * HID + hh * 64 + f;
            z[idx] = (acc[i][j] + bC[hh * 64 + f]) * dg[idx];
        }
    }
}

// ------------------- layernorm: u = z + LN(z), emits fp32 + fp16 -------------
__device__ __forceinline__ float warp_sum(float v) {
#pragma unroll
    for (int o = 16; o > 0; o >>= 1) v += __shfl_xor_sync(0xffffffffu, v, o);
    return v;
}

__global__ void __launch_bounds__(256)
ln2_k(const float* __restrict__ z, const float* __restrict__ g,
      const float* __restrict__ be, float* __restrict__ u, __half* __restrict__ uh)
{
    __shared__ float red[8];
    int row = blockIdx.x;
    int tid = threadIdx.x;
    const float* zr = z + (size_t)row * HID;
    float4 v = *(const float4*)(zr + tid * 4);

    float s = v.x + v.y + v.z + v.w;
    s = warp_sum(s);
    if ((tid & 31) == 0) red[tid >> 5] = s;
    __syncthreads();
    float tot = 0.f;
#pragma unroll
    for (int i = 0; i < 8; i++) tot += red[i];
    float mu = tot * (1.0f / HID);
    __syncthreads();

    float dx0 = v.x - mu, dx1 = v.y - mu, dx2 = v.z - mu, dx3 = v.w - mu;
    float ss = dx0*dx0 + dx1*dx1 + dx2*dx2 + dx3*dx3;
    ss = warp_sum(ss);
    if ((tid & 31) == 0) red[tid >> 5] = ss;
    __syncthreads();
    float tot2 = 0.f;
#pragma unroll
    for (int i = 0; i < 8; i++) tot2 += red[i];
    float rstd = rsqrtf(tot2 * (1.0f / HID) + EPSV);

    float4 gv = *(const float4*)(g + tid * 4);
    float4 bv = *(const float4*)(be + tid * 4);
    float4 o;
    o.x = v.x + dx0 * rstd * gv.x + bv.x;
    o.y = v.y + dx1 * rstd * gv.y + bv.y;
    o.z = v.z + dx2 * rstd * gv.z + bv.z;
    o.w = v.w + dx3 * rstd * gv.w + bv.w;
    *(float4*)(u + (size_t)row * HID + tid * 4) = o;
    *(uint2*)(uh + (size_t)row * HID + tid * 4) =
        make_uint2(pack2h(o.x, o.y), pack2h(o.z, o.w));
}

// ------------------- launch -------------------------------------------------
extern "C" void kernel_launch(void* const* d_in, const int* in_sizes, int n_in,
                              void* d_out, int out_size)
{
    const float* emb    = (const float*)d_in[0];
    const float* Wa     = (const float*)d_in[1];
    const float* ba     = (const float*)d_in[2];
    const float* Wb     = (const float*)d_in[3];
    const float* bb     = (const float*)d_in[4];
    const float* WD     = (const float*)d_in[5];
    const float* bD     = (const float*)d_in[6];
    const float* WC     = (const float*)d_in[7];
    const float* bC     = (const float*)d_in[8];
    const float* ffn1_w = (const float*)d_in[9];
    const float* ffn1_b = (const float*)d_in[10];
    const float* ffn2_w = (const float*)d_in[11];
    const float* ffn2_b = (const float*)d_in[12];
    const float* proj_w = (const float*)d_in[13];
    const float* proj_b = (const float*)d_in[14];
    const float* ln_g   = (const float*)d_in[15];
    const float* ln_b   = (const float*)d_in[16];
    float* out = (float*)d_out;

    float *pa, *pb, *pd, *ph, *pap, *pz, *pu, *paggA, *paggH, *pcarry, *pbcat;
    cudaGetSymbolAddress((void**)&pa, g_a);       cudaGetSymbolAddress((void**)&pb, g_b);
    cudaGetSymbolAddress((void**)&pd, g_d);       cudaGetSymbolAddress((void**)&ph, g_h);
    cudaGetSymbolAddress((void**)&pap, g_ap);     cudaGetSymbolAddress((void**)&pz, g_z);
    cudaGetSymbolAddress((void**)&pu, g_u);       cudaGetSymbolAddress((void**)&pbcat, g_bcat);
    cudaGetSymbolAddress((void**)&paggA, g_aggA); cudaGetSymbolAddress((void**)&paggH, g_aggH);
    cudaGetSymbolAddress((void**)&pcarry, g_carry);

    __half *pe, *puh, *pm, *pv;
    __half *wabdhi, *wabdlo, *f1hi, *f2hi, *pjhi, *pjlo;
    cudaGetSymbolAddress((void**)&pe, g_e);      cudaGetSymbolAddress((void**)&puh, g_uh);
    cudaGetSymbolAddress((void**)&pm, g_m);      cudaGetSymbolAddress((void**)&pv, g_v);
    cudaGetSymbolAddress((void**)&wabdhi, g_wabdhi);
    cudaGetSymbolAddress((void**)&wabdlo, g_wabdlo);
    cudaGetSymbolAddress((void**)&f1hi, g_f1hi); cudaGetSymbolAddress((void**)&f2hi, g_f2hi);
    cudaGetSymbolAddress((void**)&pjhi, g_pjhi); cudaGetSymbolAddress((void**)&pjlo, g_pjlo);

    const int SM_C1 = 3 * StageSz<1>::v;   // 92160
    const int SM_C0 = 3 * StageSz<0>::v;   // 61440
    cudaFuncSetAttribute((const void*)hgemm<3,0,0,1>, cudaFuncAttributeMaxDynamicSharedMemorySize, SM_C1);
    cudaFuncSetAttribute((const void*)hgemm<0,0,0,1>, cudaFuncAttributeMaxDynamicSharedMemorySize, SM_C1);
    cudaFuncSetAttribute((const void*)hgemm<2,0,1,0>, cudaFuncAttributeMaxDynamicSharedMemorySize, SM_C0);
    cudaFuncSetAttribute((const void*)hgemm<0,1,1,0>, cudaFuncAttributeMaxDynamicSharedMemorySize, SM_C0);

    // ---- prep (a/b/d GEMM is our launch #3 so ncu -s 5 lands on it) ----
    tohalf_k<<<(ROWS * HID / 4 + 255) / 256, 256>>>(emb, pe, ROWS * HID / 4);            // 0
    convT3_k<<<dim3(HID/32, HID/32, 3), dim3(32,8)>>>(Wa, Wb, WD, wabdhi, wabdlo);        // 1
    bias3_k<<<(3*HID + 255)/256, 256>>>(ba, bb, bD, pbcat);                               // 2

    // fused a|b|d = emb @ [Wa|Wb|WD] + [ba|bb|bD], tanh on a  (compensated)   // 3
    hgemm<3,0,0,1><<<dim3(3*HID/128, ROWS/128), 256, SM_C1>>>(
        pe, wabdhi, wabdlo, pbcat, nullptr, pa, nullptr, pb, pd, ROWS, 3*HID, HID);

    // remaining weight prep (overlaps with scan path)
    convT_k<<<dim3(HID/32, FF/32),  dim3(32,8)>>>(ffn1_w, f1hi, nullptr, HID, FF);
    convT_k<<<dim3(FF/32,  HID/32), dim3(32,8)>>>(ffn2_w, f2hi, nullptr, FF, HID);
    convT_k<<<dim3(HID/32, HID/32), dim3(32,8)>>>(proj_w, pjhi, pjlo, HID, HID);

    // affine scan (chunk-local + cross-chunk carries; fixup fused into head_k)
    scan1_k<<<BBAT * HH * NCHK, 64>>>(pa, pb, ph, pap, paggA, paggH);
    scan2_k<<<BBAT * HH, 64>>>(paggA, paggH, pcarry);

    // z = ((h + carry*ap) @ WC + bC) * d
    head_k<<<dim3(ROWS / 128, HH), 256>>>(ph, pap, pcarry, WC, bC, pd, pz);

    // u = z + LN(z); emit u fp32 + fp16
    ln2_k<<<ROWS, 256>>>(pz, ln_g, ln_b, pu, puh);

    // mid = gelu(u@W1 + b1) -> fp16  (uncompensated)
    hgemm<2,0,1,0><<<dim3(FF/128, ROWS/128), 256, SM_C0>>>(
        puh, f1hi, nullptr, ffn1_b, nullptr, nullptr, pm, nullptr, nullptr, ROWS, FF, HID);
    // v = mid@W2 + b2 + u -> fp16  (uncompensated)
    hgemm<0,1,1,0><<<dim3(HID/128, ROWS/128), 256, SM_C0>>>(
        pm, f2hi, nullptr, ffn2_b, pu, nullptr, pv, nullptr, nullptr, ROWS, HID, FF);
    // out = v@proj + proj_b  (compensated)
    hgemm<0,0,0,1><<<dim3(HID/128, ROWS/128), 256, SM_C1>>>(
        pv, pjhi, pjlo, proj_b, nullptr, out, nullptr, nullptr, nullptr, ROWS, HID, HID);
}

// round 12
// speedup vs baseline: 1.4510x; 1.0479x over previous
#include <cuda_runtime.h>
#include <cuda_fp16.h>
#include <math.h>
#include <stdint.h>

// Problem constants
#define BBAT 4
#define LLEN 2048
#define HH   16
#define HID  1024
#define FF   4096
#define ROWS 8192            // B*L
#define NCHK 32              // scan chunks
#define CHL  64              // scan chunk length
#define EPSV 1e-5f

// ------------------- scratch (static device memory; no allocs) ---------------
__device__ float g_a [ROWS*HID];
__device__ float g_b [ROWS*HID];
__device__ float g_d [ROWS*HID];
__device__ float g_h [ROWS*HID];
__device__ float g_ap[ROWS*HID];
__device__ float g_z [ROWS*HID];
__device__ float g_u [ROWS*HID];
__device__ float g_aggA [BBAT*HH*NCHK*64];
__device__ float g_aggH [BBAT*HH*NCHK*64];
__device__ float g_carry[BBAT*HH*NCHK*64];
__device__ float g_bcat[3*HID];

// fp16 activation buffers
__device__ __half g_e[ROWS*HID];
__device__ __half g_uh[ROWS*HID];
__device__ __half g_m[ROWS*FF];
__device__ __half g_v[ROWS*HID];
// fp16 weight buffers, transposed to [N,K]
__device__ __half g_wabdhi[3*HID*HID], g_wabdlo[3*HID*HID];  // Wa|Wb|WD stacked
__device__ __half g_f1hi[FF*HID];
__device__ __half g_f2hi[HID*FF];
__device__ __half g_pjhi[HID*HID], g_pjlo[HID*HID];

__device__ __forceinline__ float gelu_exact(float x) {
    return 0.5f * x * (1.0f + erff(x * 0.7071067811865476f));
}
__device__ __forceinline__ uint32_t pack2h(float a, float b) {
    __half2 t = __floats2half2_rn(a, b);
    return *(uint32_t*)&t;
}
__device__ __forceinline__ uint32_t smem_u32(const void* p) {
    uint32_t a;
    asm("{ .reg .u64 t; cvta.to.shared.u64 t, %1; cvt.u32.u64 %0, t; }" : "=r"(a) : "l"(p));
    return a;
}

#define MMA_OP(d, a, b) \
    asm volatile("mma.sync.aligned.m16n8k16.row.col.f32.f16.f16.f32 " \
                 "{%0,%1,%2,%3},{%4,%5,%6,%7},{%8,%9},{%0,%1,%2,%3};" \
                 : "+f"((d)[0]), "+f"((d)[1]), "+f"((d)[2]), "+f"((d)[3]) \
                 : "r"((a)[0]), "r"((a)[1]), "r"((a)[2]), "r"((a)[3]), \
                   "r"((b)[0]), "r"((b)[1]))

#define LDSM4(r, addr) \
    asm volatile("ldmatrix.sync.aligned.m8n8.x4.shared.b16 {%0,%1,%2,%3}, [%4];" \
                 : "=r"((r)[0]), "=r"((r)[1]), "=r"((r)[2]), "=r"((r)[3]) : "r"(addr))

#define CP16(dst, src) \
    asm volatile("cp.async.cg.shared.global [%0], [%1], 16;" :: "r"(dst), "l"(src))

// ------------------- fp16 compensated GEMM -----------------------------------
// C[M,N] = epi(A @ (Bh[+Bl])^T + bias) (+res). A=[M,K] fp16, Bh/Bl=[N,K] fp16.
// Block 128x128xCK, 3-stage cp.async pipeline, 8 warps (2m x 4n), 2 CTA/SM.
// COMP=1: two MMAs (hi+lo weights), CK=32. COMP=0: single MMA, CK=64.
// EPI: 0 none, 1 tanh, 2 gelu, 3 = fused a/b/d (column-sectioned, tanh sec 0).
// OUT=0: fp32 Cf. OUT=1: fp16 Chf. OUT=2: both.

template<int COMP, int CK>
__device__ __forceinline__ void issue_stage(
    uint32_t base, int tid, int m0, int n0, int k0, int K,
    const __half* Ag, const __half* Bhg, const __half* Blg)
{
    const int PADB = 2 * CK + 16;
    const int CPT = CK / 8;                // 16B chunks per row
    const int ITER = 128 * CPT / 256;      // fill iterations per tile
#pragma unroll
    for (int r = 0; r < ITER; r++) {
        int id = tid + r * 256;
        int row = id / CPT, ch = id % CPT;
        uint32_t d = base + row * PADB + ch * 16;
        size_t ga = (size_t)(m0 + row) * K + k0 + ch * 8;
        size_t gb = (size_t)(n0 + row) * K + k0 + ch * 8;
        CP16(d, Ag + ga);
        CP16(d + 128 * PADB, Bhg + gb);
        if (COMP) CP16(d + 256 * PADB, Blg + gb);
    }
    asm volatile("cp.async.commit_group;");
}

template<int EPI, int RES, int OUT, int COMP, int CK>
__global__ void __launch_bounds__(256, 2)
hgemm(const __half* __restrict__ Ag,
      const __half* __restrict__ Bhg, const __half* __restrict__ Blg,
      const float* __restrict__ bias, const float* __restrict__ res,
      float* __restrict__ Cf, __half* __restrict__ Chf,
      float* __restrict__ Cf2, float* __restrict__ Cf3,
      int M, int N, int K)
{
    const int PADB = 2 * CK + 16;
    const int BHOFF = 128 * PADB;
    const int STG_SZ = (COMP ? 3 : 2) * 128 * PADB;
    extern __shared__ __align__(16) char sm[];
    const uint32_t sb = smem_u32(sm);
    const int tid = threadIdx.x;
    const int m0 = blockIdx.y * 128;
    const int n0 = blockIdx.x * 128;
    const int lane = tid & 31;
    const int wid = tid >> 5;
    const int wm = (wid & 1) * 64;
    const int wn = (wid >> 1) * 32;
    const int g = lane >> 2;
    const int t = lane & 3;
    const int q = lane >> 3;
    const int rr8 = lane & 7;

    float acc[4][4][4];
#pragma unroll
    for (int i = 0; i < 4; i++)
#pragma unroll
        for (int j = 0; j < 4; j++)
#pragma unroll
            for (int r = 0; r < 4; r++) acc[i][j][r] = 0.f;

    const int nch = K / CK;
    issue_stage<COMP, CK>(sb,          tid, m0, n0, 0,  K, Ag, Bhg, Blg);
    issue_stage<COMP, CK>(sb + STG_SZ, tid, m0, n0, CK, K, Ag, Bhg, Blg);

    const uint32_t a_lane = (uint32_t)((wm + ((q & 1) << 3) + rr8) * PADB + ((q >> 1) << 3) * 2);
    const uint32_t b_lane = (uint32_t)((wn + ((q >> 1) << 3) + rr8) * PADB + ((q & 1) << 3) * 2) + BHOFF;

    int stg = 0;
    for (int c = 0; c < nch; c++) {
        const uint32_t base = sb + stg * STG_SZ;
        if (c + 1 < nch) asm volatile("cp.async.wait_group 1;");
        else             asm volatile("cp.async.wait_group 0;");
        __syncthreads();
        if (c + 2 < nch) {
            int ns = stg + 2; if (ns >= 3) ns -= 3;
            issue_stage<COMP, CK>(sb + ns * STG_SZ, tid, m0, n0, (c + 2) * CK, K, Ag, Bhg, Blg);
        }

#pragma unroll
        for (int ks = 0; ks < CK; ks += 16) {
            uint32_t bh[2][4], bl[2][4];
#pragma unroll
            for (int p = 0; p < 2; p++) {
                uint32_t ad = base + b_lane + (uint32_t)(p * 16 * PADB + ks * 2);
                LDSM4(bh[p], ad);
                if (COMP) LDSM4(bl[p], ad + 128 * PADB);
            }
#pragma unroll
            for (int mt = 0; mt < 4; mt++) {
                uint32_t ad = base + a_lane + (uint32_t)(mt * 16 * PADB + ks * 2);
                uint32_t ah[4];
                LDSM4(ah, ad);
#pragma unroll
                for (int nt = 0; nt < 4; nt++) {
                    uint32_t* bhp = &bh[nt >> 1][(nt & 1) * 2];
                    MMA_OP(acc[mt][nt], ah, bhp);
                    if (COMP) {
                        uint32_t* blp = &bl[nt >> 1][(nt & 1) * 2];
                        MMA_OP(acc[mt][nt], ah, blp);
                    }
                }
            }
        }
        stg++; if (stg >= 3) stg = 0;
    }

    // ---- epilogue ----
#pragma unroll
    for (int mt = 0; mt < 4; mt++) {
#pragma unroll
        for (int nt = 0; nt < 4; nt++) {
            int row0 = m0 + wm + mt * 16 + g;
            int col = n0 + wn + nt * 8 + t * 2;
            float b0 = __ldg(bias + col), b1 = __ldg(bias + col + 1);
#pragma unroll
            for (int half = 0; half < 2; half++) {
                int rw = row0 + half * 8;
                float v0 = acc[mt][nt][half * 2 + 0] + b0;
                float v1 = acc[mt][nt][half * 2 + 1] + b1;
                if (EPI == 3) {
                    int sec = col >> 10;
                    int lc = col & 1023;
                    if (sec == 0) { v0 = tanhf(v0); v1 = tanhf(v1); }
                    float* dst = (sec == 0) ? Cf : ((sec == 1) ? Cf2 : Cf3);
                    float2 o; o.x = v0; o.y = v1;
                    *(float2*)(dst + (size_t)rw * HID + lc) = o;
                } else {
                    if (EPI == 1) { v0 = tanhf(v0); v1 = tanhf(v1); }
                    else if (EPI == 2) { v0 = gelu_exact(v0); v1 = gelu_exact(v1); }
                    if (RES) {
                        const float2 rv = *(const float2*)(res + (size_t)rw * N + col);
                        v0 += rv.x; v1 += rv.y;
                    }
                    if (OUT == 0 || OUT == 2) {
                        float2 o; o.x = v0; o.y = v1;
                        *(float2*)(Cf + (size_t)rw * N + col) = o;
                    }
                    if (OUT == 1 || OUT == 2) {
                        *(uint32_t*)(Chf + (size_t)rw * N + col) = pack2h(v0, v1);
                    }
                }
            }
        }
    }
}

// ------------------- conversion kernels --------------------------------------
__global__ void tohalf_k(const float* __restrict__ in, __half* __restrict__ o, int nvec)
{
    int i = blockIdx.x * blockDim.x + threadIdx.x;
    if (i >= nvec) return;
    float4 v = ((const float4*)in)[i];
    uint2 p = make_uint2(pack2h(v.x, v.y), pack2h(v.z, v.w));
    ((uint2*)o)[i] = p;
}

// transpose+split for the 3 stacked [H,K,64] weights -> [3*HID, K] hi/lo
__global__ void convT3_k(const float* __restrict__ w0, const float* __restrict__ w1,
                         const float* __restrict__ w2,
                         __half* __restrict__ hi, __half* __restrict__ lo)
{
    __shared__ float t[32][33];
    const float* in = (blockIdx.z == 0) ? w0 : (blockIdx.z == 1) ? w1 : w2;
    __half* hip = hi + (size_t)blockIdx.z * HID * HID;
    __half* lop = lo + (size_t)blockIdx.z * HID * HID;
    int k0 = blockIdx.x * 32, n0 = blockIdx.y * 32;
    int tx = threadIdx.x, ty = threadIdx.y;
    for (int r = ty; r < 32; r += 8) {
        int k = k0 + r, n = n0 + tx;
        t[r][tx] = in[((size_t)(n >> 6) * HID + k) * 64 + (n & 63)];
    }
    __syncthreads();
    for (int r = ty; r < 32; r += 8) {
        int n = n0 + r, k = k0 + tx;
        float v = t[tx][r];
        __half h = __float2half_rn(v);
        hip[(size_t)n * HID + k] = h;
        lop[(size_t)n * HID + k] = __float2half_rn(v - __half2float(h));
    }
}

__global__ void bias3_k(const float* __restrict__ b0, const float* __restrict__ b1,
                        const float* __restrict__ b2, float* __restrict__ o)
{
    int i = blockIdx.x * blockDim.x + threadIdx.x;
    if (i >= 3 * HID) return;
    o[i] = (i < HID) ? b0[i] : (i < 2 * HID) ? b1[i - HID] : b2[i - 2 * HID];
}

// transpose+split: out[n][k] = in(k,n); in [K,N] row-major
__global__ void convT_k(const float* __restrict__ in, __half* __restrict__ hi,
                        __half* __restrict__ lo, int K, int N)
{
    __shared__ float t[32][33];
    int k0 = blockIdx.x * 32, n0 = blockIdx.y * 32;
    int tx = threadIdx.x, ty = threadIdx.y;
    for (int r = ty; r < 32; r += 8) {
        int k = k0 + r, n = n0 + tx;
        t[r][tx] = in[(size_t)k * N + n];
    }
    __syncthreads();
    for (int r = ty; r < 32; r += 8) {
        int n = n0 + r, k = k0 + tx;
        float v = t[tx][r];
        __half h = __float2half_rn(v);
        hi[(size_t)n * K + k] = h;
        if (lo) lo[(size_t)n * K + k] = __float2half_rn(v - __half2float(h));
    }
}

// ------------------- scan kernels -------------------------------------------
__global__ void scan1_k(const float* __restrict__ a, const float* __restrict__ b,
                        float* __restrict__ hout, float* __restrict__ apre,
                        float* __restrict__ aggA, float* __restrict__ aggH)
{
    int blk = blockIdx.x;
    int c = blk & (NCHK - 1);
    int bh = blk >> 5;
    int hh = bh & (HH - 1);
    int bb = bh >> 4;
    int d = threadIdx.x;
    int l0 = c * CHL;
    float A = 1.f, Hl = 0.f;
#pragma unroll 4
    for (int t = 0; t < CHL; t++) {
        size_t idx = (size_t)(bb * LLEN + l0 + t) * HID + hh * 64 + d;
        float av = a[idx], bv = b[idx];
        Hl = fmaf(av, Hl, bv);
        A *= av;
        hout[idx] = Hl;
        apre[idx] = A;
    }
    int ai = (bh * NCHK + c) * 64 + d;
    aggA[ai] = A;
    aggH[ai] = Hl;
}

__global__ void scan2_k(const float* __restrict__ aggA, const float* __restrict__ aggH,
                        float* __restrict__ carry)
{
    int bh = blockIdx.x;
    int d = threadIdx.x;
    float c = 0.f;
#pragma unroll
    for (int ch = 0; ch < NCHK; ch++) {
        int ai = (bh * NCHK + ch) * 64 + d;
        carry[ai] = c;
        c = fmaf(aggA[ai], c, aggH[ai]);
    }
}

// ------------------- per-head GEMM with fused scan fixup ----------------------
// z = ((h + carry*ap) @ WC[h] + bC[h]) * d
__global__ void __launch_bounds__(256)
head_k(const float* __restrict__ hmat, const float* __restrict__ apre,
       const float* __restrict__ carry,
       const float* __restrict__ WC, const float* __restrict__ bC,
       const float* __restrict__ dg, float* __restrict__ z)
{
    __shared__ float Ws[64][65];
    __shared__ float Hs[64][129];
    int hh = blockIdx.y;
    int r0 = blockIdx.x * 128;
    int tid = threadIdx.x;

    const float* wp = WC + (size_t)hh * 64 * 64;
    for (int id = tid; id < 1024; id += 256) {
        int k = id >> 4; int f = (id & 15) * 4;
        float4 v = *(const float4*)(wp + k * 64 + f);
        Ws[k][f] = v.x; Ws[k][f+1] = v.y; Ws[k][f+2] = v.z; Ws[k][f+3] = v.w;
    }
    for (int id = tid; id < 2048; id += 256) {
        int row = id >> 4; int d4 = (id & 15) * 4;
        int rg = r0 + row;
        size_t gi = (size_t)rg * HID + hh * 64 + d4;
        float4 v  = *(const float4*)(hmat + gi);
        float4 ap = *(const float4*)(apre + gi);
        int bb = rg >> 11, l = rg & (LLEN - 1), cc = l >> 6;
        int ai = (((bb * HH + hh) * NCHK) + cc) * 64 + d4;
        float4 cr = *(const float4*)(carry + ai);
        Hs[d4][row]   = fmaf(cr.x, ap.x, v.x);
        Hs[d4+1][row] = fmaf(cr.y, ap.y, v.y);
        Hs[d4+2][row] = fmaf(cr.z, ap.z, v.z);
        Hs[d4+3][row] = fmaf(cr.w, ap.w, v.w);
    }
    __syncthreads();

    int tx = tid & 15, ty = tid >> 4;
    float acc[8][4];
#pragma unroll
    for (int i = 0; i < 8; i++)
#pragma unroll
        for (int j = 0; j < 4; j++) acc[i][j] = 0.f;

#pragma unroll 8
    for (int k = 0; k < 64; k++) {
        float ar[8], br[4];
#pragma unroll
        for (int i = 0; i < 8; i++) ar[i] = Hs[k][ty * 8 + i];
#pragma unroll
        for (int j = 0; j < 4; j++) br[j] = Ws[k][tx * 4 + j];
#pragma unroll
        for (int i = 0; i < 8; i++)
#pragma unroll
            for (int j = 0; j < 4; j++)
                acc[i][j] = fmaf(ar[i], br[j], acc[i][j]);
    }
#pragma unroll
    for (int i = 0; i < 8; i++) {
        int row = r0 + ty * 8 + i;
#pragma unroll
        for (int j = 0; j < 4; j++) {
            int f = tx * 4 + j;
            size_t idx = (size_t)row * HID + hh * 64 + f;
            z[idx] = (acc[i][j] + bC[hh * 64 + f]) * dg[idx];
        }
    }
}

// ------------------- layernorm: u = z + LN(z), emits fp32 + fp16 -------------
__device__ __forceinline__ float warp_sum(float v) {
#pragma unroll
    for (int o = 16; o > 0; o >>= 1) v += __shfl_xor_sync(0xffffffffu, v, o);
    return v;
}

__global__ void __launch_bounds__(256)
ln2_k(const float* __restrict__ z, const float* __restrict__ g,
      const float* __restrict__ be, float* __restrict__ u, __half* __restrict__ uh)
{
    __shared__ float red[8];
    int row = blockIdx.x;
    int tid = threadIdx.x;
    const float* zr = z + (size_t)row * HID;
    float4 v = *(const float4*)(zr + tid * 4);

    float s = v.x + v.y + v.z + v.w;
    s = warp_sum(s);
    if ((tid & 31) == 0) red[tid >> 5] = s;
    __syncthreads();
    float tot = 0.f;
#pragma unroll
    for (int i = 0; i < 8; i++) tot += red[i];
    float mu = tot * (1.0f / HID);
    __syncthreads();

    float dx0 = v.x - mu, dx1 = v.y - mu, dx2 = v.z - mu, dx3 = v.w - mu;
    float ss = dx0*dx0 + dx1*dx1 + dx2*dx2 + dx3*dx3;
    ss = warp_sum(ss);
    if ((tid & 31) == 0) red[tid >> 5] = ss;
    __syncthreads();
    float tot2 = 0.f;
#pragma unroll
    for (int i = 0; i < 8; i++) tot2 += red[i];
    float rstd = rsqrtf(tot2 * (1.0f / HID) + EPSV);

    float4 gv = *(const float4*)(g + tid * 4);
    float4 bv = *(const float4*)(be + tid * 4);
    float4 o;
    o.x = v.x + dx0 * rstd * gv.x + bv.x;
    o.y = v.y + dx1 * rstd * gv.y + bv.y;
    o.z = v.z + dx2 * rstd * gv.z + bv.z;
    o.w = v.w + dx3 * rstd * gv.w + bv.w;
    *(float4*)(u + (size_t)row * HID + tid * 4) = o;
    *(uint2*)(uh + (size_t)row * HID + tid * 4) =
        make_uint2(pack2h(o.x, o.y), pack2h(o.z, o.w));
}

// ------------------- launch -------------------------------------------------
extern "C" void kernel_launch(void* const* d_in, const int* in_sizes, int n_in,
                              void* d_out, int out_size)
{
    const float* emb    = (const float*)d_in[0];
    const float* Wa     = (const float*)d_in[1];
    const float* ba     = (const float*)d_in[2];
    const float* Wb     = (const float*)d_in[3];
    const float* bb     = (const float*)d_in[4];
    const float* WD     = (const float*)d_in[5];
    const float* bD     = (const float*)d_in[6];
    const float* WC     = (const float*)d_in[7];
    const float* bC     = (const float*)d_in[8];
    const float* ffn1_w = (const float*)d_in[9];
    const float* ffn1_b = (const float*)d_in[10];
    const float* ffn2_w = (const float*)d_in[11];
    const float* ffn2_b = (const float*)d_in[12];
    const float* proj_w = (const float*)d_in[13];
    const float* proj_b = (const float*)d_in[14];
    const float* ln_g   = (const float*)d_in[15];
    const float* ln_b   = (const float*)d_in[16];
    float* out = (float*)d_out;

    float *pa, *pb, *pd, *ph, *pap, *pz, *pu, *paggA, *paggH, *pcarry, *pbcat;
    cudaGetSymbolAddress((void**)&pa, g_a);       cudaGetSymbolAddress((void**)&pb, g_b);
    cudaGetSymbolAddress((void**)&pd, g_d);       cudaGetSymbolAddress((void**)&ph, g_h);
    cudaGetSymbolAddress((void**)&pap, g_ap);     cudaGetSymbolAddress((void**)&pz, g_z);
    cudaGetSymbolAddress((void**)&pu, g_u);       cudaGetSymbolAddress((void**)&pbcat, g_bcat);
    cudaGetSymbolAddress((void**)&paggA, g_aggA); cudaGetSymbolAddress((void**)&paggH, g_aggH);
    cudaGetSymbolAddress((void**)&pcarry, g_carry);

    __half *pe, *puh, *pm, *pv;
    __half *wabdhi, *wabdlo, *f1hi, *f2hi, *pjhi, *pjlo;
    cudaGetSymbolAddress((void**)&pe, g_e);      cudaGetSymbolAddress((void**)&puh, g_uh);
    cudaGetSymbolAddress((void**)&pm, g_m);      cudaGetSymbolAddress((void**)&pv, g_v);
    cudaGetSymbolAddress((void**)&wabdhi, g_wabdhi);
    cudaGetSymbolAddress((void**)&wabdlo, g_wabdlo);
    cudaGetSymbolAddress((void**)&f1hi, g_f1hi); cudaGetSymbolAddress((void**)&f2hi, g_f2hi);
    cudaGetSymbolAddress((void**)&pjhi, g_pjhi); cudaGetSymbolAddress((void**)&pjlo, g_pjlo);

    const int SM_C1 = 3 * 3 * 128 * 80;    // COMP=1, CK=32: 92160
    const int SM_C0 = 3 * 2 * 128 * 144;   // COMP=0, CK=64: 110592
    cudaFuncSetAttribute((const void*)hgemm<3,0,0,1,32>, cudaFuncAttributeMaxDynamicSharedMemorySize, SM_C1);
    cudaFuncSetAttribute((const void*)hgemm<0,0,0,1,32>, cudaFuncAttributeMaxDynamicSharedMemorySize, SM_C1);
    cudaFuncSetAttribute((const void*)hgemm<2,0,1,0,64>, cudaFuncAttributeMaxDynamicSharedMemorySize, SM_C0);
    cudaFuncSetAttribute((const void*)hgemm<0,1,1,0,64>, cudaFuncAttributeMaxDynamicSharedMemorySize, SM_C0);

    // ---- prep (a/b/d GEMM stays launch #3 for the ncu capture slot) ----
    tohalf_k<<<(ROWS * HID / 4 + 255) / 256, 256>>>(emb, pe, ROWS * HID / 4);            // 0
    convT3_k<<<dim3(HID/32, HID/32, 3), dim3(32,8)>>>(Wa, Wb, WD, wabdhi, wabdlo);        // 1
    bias3_k<<<(3*HID + 255)/256, 256>>>(ba, bb, bD, pbcat);                               // 2

    // fused a|b|d = emb @ [Wa|Wb|WD] + [ba|bb|bD], tanh on a  (compensated)   // 3
    hgemm<3,0,0,1,32><<<dim3(3*HID/128, ROWS/128), 256, SM_C1>>>(
        pe, wabdhi, wabdlo, pbcat, nullptr, pa, nullptr, pb, pd, ROWS, 3*HID, HID);

    // remaining weight prep (overlaps with scan path)
    convT_k<<<dim3(HID/32, FF/32),  dim3(32,8)>>>(ffn1_w, f1hi, nullptr, HID, FF);
    convT_k<<<dim3(FF/32,  HID/32), dim3(32,8)>>>(ffn2_w, f2hi, nullptr, FF, HID);
    convT_k<<<dim3(HID/32, HID/32), dim3(32,8)>>>(proj_w, pjhi, pjlo, HID, HID);

    // affine scan (chunk-local + cross-chunk carries; fixup fused into head_k)
    scan1_k<<<BBAT * HH * NCHK, 64>>>(pa, pb, ph, pap, paggA, paggH);
    scan2_k<<<BBAT * HH, 64>>>(paggA, paggH, pcarry);

    // z = ((h + carry*ap) @ WC + bC) * d
    head_k<<<dim3(ROWS / 128, HH), 256>>>(ph, pap, pcarry, WC, bC, pd, pz);

    // u = z + LN(z); emit u fp32 + fp16
    ln2_k<<<ROWS, 256>>>(pz, ln_g, ln_b, pu, puh);

    // mid = gelu(u@W1 + b1) -> fp16  (uncompensated, CK=64: half the syncs)
    hgemm<2,0,1,0,64><<<dim3(FF/128, ROWS/128), 256, SM_C0>>>(
        puh, f1hi, nullptr, ffn1_b, nullptr, nullptr, pm, nullptr, nullptr, ROWS, FF, HID);
    // v = mid@W2 + b2 + u -> fp16  (uncompensated, CK=64)
    hgemm<0,1,1,0,64><<<dim3(HID/128, ROWS/128), 256, SM_C0>>>(
        pm, f2hi, nullptr, ffn2_b, pu, nullptr, pv, nullptr, nullptr, ROWS, HID, FF);
    // out = v@proj + proj_b  (compensated)
    hgemm<0,0,0,1,32><<<dim3(HID/128, ROWS/128), 256, SM_C1>>>(
        pv, pjhi, pjlo, proj_b, nullptr, out, nullptr, nullptr, nullptr, ROWS, HID, HID);
}

// round 13
// speedup vs baseline: 1.6752x; 1.1545x over previous
#include <cuda_runtime.h>
#include <cuda_fp16.h>
#include <math.h>
#include <stdint.h>

// Problem constants
#define BBAT 4
#define LLEN 2048
#define HH   16
#define HID  1024
#define FF   4096
#define ROWS 8192            // B*L
#define NCHK 32              // scan chunks
#define CHL  64              // scan chunk length
#define EPSV 1e-5f

// ------------------- scratch (static device memory; no allocs) ---------------
__device__ float g_a [ROWS*HID];
__device__ float g_b [ROWS*HID];
__device__ float g_d [ROWS*HID];
__device__ float g_h [ROWS*HID];
__device__ float g_ap[ROWS*HID];
__device__ float g_z [ROWS*HID];
__device__ float g_u [ROWS*HID];
__device__ float g_aggA [BBAT*HH*NCHK*64];
__device__ float g_aggH [BBAT*HH*NCHK*64];
__device__ float g_carry[BBAT*HH*NCHK*64];
__device__ float g_bcat[3*HID];

// fp16 activation buffers
__device__ __half g_e[ROWS*HID];
__device__ __half g_uh[ROWS*HID];
__device__ __half g_m[ROWS*FF];
__device__ __half g_v[ROWS*HID];
// fp16 weight buffers, transposed to [N,K]
__device__ __half g_wabdhi[3*HID*HID], g_wabdlo[3*HID*HID];  // Wa|Wb|WD stacked (lo used for Wa only)
__device__ __half g_f1hi[FF*HID];
__device__ __half g_f2hi[HID*FF];
__device__ __half g_pjhi[HID*HID];

__device__ __forceinline__ float gelu_exact(float x) {
    return 0.5f * x * (1.0f + erff(x * 0.7071067811865476f));
}
__device__ __forceinline__ uint32_t pack2h(float a, float b) {
    __half2 t = __floats2half2_rn(a, b);
    return *(uint32_t*)&t;
}
__device__ __forceinline__ uint32_t smem_u32(const void* p) {
    uint32_t a;
    asm("{ .reg .u64 t; cvta.to.shared.u64 t, %1; cvt.u32.u64 %0, t; }" : "=r"(a) : "l"(p));
    return a;
}

#define MMA_OP(d, a, b) \
    asm volatile("mma.sync.aligned.m16n8k16.row.col.f32.f16.f16.f32 " \
                 "{%0,%1,%2,%3},{%4,%5,%6,%7},{%8,%9},{%0,%1,%2,%3};" \
                 : "+f"((d)[0]), "+f"((d)[1]), "+f"((d)[2]), "+f"((d)[3]) \
                 : "r"((a)[0]), "r"((a)[1]), "r"((a)[2]), "r"((a)[3]), \
                   "r"((b)[0]), "r"((b)[1]))

#define LDSM4(r, addr) \
    asm volatile("ldmatrix.sync.aligned.m8n8.x4.shared.b16 {%0,%1,%2,%3}, [%4];" \
                 : "=r"((r)[0]), "=r"((r)[1]), "=r"((r)[2]), "=r"((r)[3]) : "r"(addr))

#define CP16(dst, src) \
    asm volatile("cp.async.cg.shared.global [%0], [%1], 16;" :: "r"(dst), "l"(src))

// ------------------- fp16 compensated GEMM -----------------------------------
// C[M,N] = epi(A @ (Bh[+Bl])^T + bias) (+res). A=[M,K] fp16, Bh/Bl=[N,K] fp16.
// Block 128x128xCK, 3-stage cp.async pipeline, 8 warps (2m x 4n), 2 CTA/SM.
// COMP=1: two MMAs (hi+lo weights), CK=32. COMP=0: single MMA, CK=64.
// EPI: 0 none, 1 tanh, 2 gelu,
//      3 = 2-section fused b/d epilogue (col>>10 selects Cf / Cf2, no act).
// OUT=0: fp32 Cf. OUT=1: fp16 Chf. OUT=2: both.

template<int COMP, int CK>
__device__ __forceinline__ void issue_stage(
    uint32_t base, int tid, int m0, int n0, int k0, int K,
    const __half* Ag, const __half* Bhg, const __half* Blg)
{
    const int PADB = 2 * CK + 16;
    const int CPT = CK / 8;                // 16B chunks per row
    const int ITER = 128 * CPT / 256;      // fill iterations per tile
#pragma unroll
    for (int r = 0; r < ITER; r++) {
        int id = tid + r * 256;
        int row = id / CPT, ch = id % CPT;
        uint32_t d = base + row * PADB + ch * 16;
        size_t ga = (size_t)(m0 + row) * K + k0 + ch * 8;
        size_t gb = (size_t)(n0 + row) * K + k0 + ch * 8;
        CP16(d, Ag + ga);
        CP16(d + 128 * PADB, Bhg + gb);
        if (COMP) CP16(d + 256 * PADB, Blg + gb);
    }
    asm volatile("cp.async.commit_group;");
}

template<int EPI, int RES, int OUT, int COMP, int CK>
__global__ void __launch_bounds__(256, 2)
hgemm(const __half* __restrict__ Ag,
      const __half* __restrict__ Bhg, const __half* __restrict__ Blg,
      const float* __restrict__ bias, const float* __restrict__ res,
      float* __restrict__ Cf, __half* __restrict__ Chf,
      float* __restrict__ Cf2,
      int M, int N, int K)
{
    const int PADB = 2 * CK + 16;
    const int BHOFF = 128 * PADB;
    const int STG_SZ = (COMP ? 3 : 2) * 128 * PADB;
    extern __shared__ __align__(16) char sm[];
    const uint32_t sb = smem_u32(sm);
    const int tid = threadIdx.x;
    const int m0 = blockIdx.y * 128;
    const int n0 = blockIdx.x * 128;
    const int lane = tid & 31;
    const int wid = tid >> 5;
    const int wm = (wid & 1) * 64;
    const int wn = (wid >> 1) * 32;
    const int g = lane >> 2;
    const int t = lane & 3;
    const int q = lane >> 3;
    const int rr8 = lane & 7;

    float acc[4][4][4];
#pragma unroll
    for (int i = 0; i < 4; i++)
#pragma unroll
        for (int j = 0; j < 4; j++)
#pragma unroll
            for (int r = 0; r < 4; r++) acc[i][j][r] = 0.f;

    const int nch = K / CK;
    issue_stage<COMP, CK>(sb,          tid, m0, n0, 0,  K, Ag, Bhg, Blg);
    issue_stage<COMP, CK>(sb + STG_SZ, tid, m0, n0, CK, K, Ag, Bhg, Blg);

    const uint32_t a_lane = (uint32_t)((wm + ((q & 1) << 3) + rr8) * PADB + ((q >> 1) << 3) * 2);
    const uint32_t b_lane = (uint32_t)((wn + ((q >> 1) << 3) + rr8) * PADB + ((q & 1) << 3) * 2) + BHOFF;

    int stg = 0;
    for (int c = 0; c < nch; c++) {
        const uint32_t base = sb + stg * STG_SZ;
        if (c + 1 < nch) asm volatile("cp.async.wait_group 1;");
        else             asm volatile("cp.async.wait_group 0;");
        __syncthreads();
        if (c + 2 < nch) {
            int ns = stg + 2; if (ns >= 3) ns -= 3;
            issue_stage<COMP, CK>(sb + ns * STG_SZ, tid, m0, n0, (c + 2) * CK, K, Ag, Bhg, Blg);
        }

#pragma unroll
        for (int ks = 0; ks < CK; ks += 16) {
            uint32_t bh[2][4], bl[2][4];
#pragma unroll
            for (int p = 0; p < 2; p++) {
                uint32_t ad = base + b_lane + (uint32_t)(p * 16 * PADB + ks * 2);
                LDSM4(bh[p], ad);
                if (COMP) LDSM4(bl[p], ad + 128 * PADB);
            }
#pragma unroll
            for (int mt = 0; mt < 4; mt++) {
                uint32_t ad = base + a_lane + (uint32_t)(mt * 16 * PADB + ks * 2);
                uint32_t ah[4];
                LDSM4(ah, ad);
#pragma unroll
                for (int nt = 0; nt < 4; nt++) {
                    uint32_t* bhp = &bh[nt >> 1][(nt & 1) * 2];
                    MMA_OP(acc[mt][nt], ah, bhp);
                    if (COMP) {
                        uint32_t* blp = &bl[nt >> 1][(nt & 1) * 2];
                        MMA_OP(acc[mt][nt], ah, blp);
                    }
                }
            }
        }
        stg++; if (stg >= 3) stg = 0;
    }

    // ---- epilogue ----
#pragma unroll
    for (int mt = 0; mt < 4; mt++) {
#pragma unroll
        for (int nt = 0; nt < 4; nt++) {
            int row0 = m0 + wm + mt * 16 + g;
            int col = n0 + wn + nt * 8 + t * 2;
            float b0 = __ldg(bias + col), b1 = __ldg(bias + col + 1);
#pragma unroll
            for (int half = 0; half < 2; half++) {
                int rw = row0 + half * 8;
                float v0 = acc[mt][nt][half * 2 + 0] + b0;
                float v1 = acc[mt][nt][half * 2 + 1] + b1;
                if (EPI == 3) {
                    // fused b/d: 2 column sections of HID, no activation
                    float* dst = (col >> 10) ? Cf2 : Cf;
                    float2 o; o.x = v0; o.y = v1;
                    *(float2*)(dst + (size_t)rw * HID + (col & 1023)) = o;
                } else {
                    if (EPI == 1) { v0 = tanhf(v0); v1 = tanhf(v1); }
                    else if (EPI == 2) { v0 = gelu_exact(v0); v1 = gelu_exact(v1); }
                    if (RES) {
                        const float2 rv = *(const float2*)(res + (size_t)rw * N + col);
                        v0 += rv.x; v1 += rv.y;
                    }
                    if (OUT == 0 || OUT == 2) {
                        float2 o; o.x = v0; o.y = v1;
                        *(float2*)(Cf + (size_t)rw * N + col) = o;
                    }
                    if (OUT == 1 || OUT == 2) {
                        *(uint32_t*)(Chf + (size_t)rw * N + col) = pack2h(v0, v1);
                    }
                }
            }
        }
    }
}

// ------------------- conversion kernels --------------------------------------
__global__ void tohalf_k(const float* __restrict__ in, __half* __restrict__ o, int nvec)
{
    int i = blockIdx.x * blockDim.x + threadIdx.x;
    if (i >= nvec) return;
    float4 v = ((const float4*)in)[i];
    uint2 p = make_uint2(pack2h(v.x, v.y), pack2h(v.z, v.w));
    ((uint2*)o)[i] = p;
}

// transpose+split for the 3 stacked [H,K,64] weights -> [3*HID, K] hi/lo
__global__ void convT3_k(const float* __restrict__ w0, const float* __restrict__ w1,
                         const float* __restrict__ w2,
                         __half* __restrict__ hi, __half* __restrict__ lo)
{
    __shared__ float t[32][33];
    const float* in = (blockIdx.z == 0) ? w0 : (blockIdx.z == 1) ? w1 : w2;
    __half* hip = hi + (size_t)blockIdx.z * HID * HID;
    __half* lop = lo + (size_t)blockIdx.z * HID * HID;
    int k0 = blockIdx.x * 32, n0 = blockIdx.y * 32;
    int tx = threadIdx.x, ty = threadIdx.y;
    for (int r = ty; r < 32; r += 8) {
        int k = k0 + r, n = n0 + tx;
        t[r][tx] = in[((size_t)(n >> 6) * HID + k) * 64 + (n & 63)];
    }
    __syncthreads();
    for (int r = ty; r < 32; r += 8) {
        int n = n0 + r, k = k0 + tx;
        float v = t[tx][r];
        __half h = __float2half_rn(v);
        hip[(size_t)n * HID + k] = h;
        lop[(size_t)n * HID + k] = __float2half_rn(v - __half2float(h));
    }
}

__global__ void bias3_k(const float* __restrict__ b0, const float* __restrict__ b1,
                        const float* __restrict__ b2, float* __restrict__ o)
{
    int i = blockIdx.x * blockDim.x + threadIdx.x;
    if (i >= 3 * HID) return;
    o[i] = (i < HID) ? b0[i] : (i < 2 * HID) ? b1[i - HID] : b2[i - 2 * HID];
}

// transpose+split: out[n][k] = in(k,n); in [K,N] row-major
__global__ void convT_k(const float* __restrict__ in, __half* __restrict__ hi,
                        __half* __restrict__ lo, int K, int N)
{
    __shared__ float t[32][33];
    int k0 = blockIdx.x * 32, n0 = blockIdx.y * 32;
    int tx = threadIdx.x, ty = threadIdx.y;
    for (int r = ty; r < 32; r += 8) {
        int k = k0 + r, n = n0 + tx;
        t[r][tx] = in[(size_t)k * N + n];
    }
    __syncthreads();
    for (int r = ty; r < 32; r += 8) {
        int n = n0 + r, k = k0 + tx;
        float v = t[tx][r];
        __half h = __float2half_rn(v);
        hi[(size_t)n * K + k] = h;
        if (lo) lo[(size_t)n * K + k] = __float2half_rn(v - __half2float(h));
    }
}

// ------------------- scan kernels -------------------------------------------
__global__ void scan1_k(const float* __restrict__ a, const float* __restrict__ b,
                        float* __restrict__ hout, float* __restrict__ apre,
                        float* __restrict__ aggA, float* __restrict__ aggH)
{
    int blk = blockIdx.x;
    int c = blk & (NCHK - 1);
    int bh = blk >> 5;
    int hh = bh & (HH - 1);
    int bb = bh >> 4;
    int d = threadIdx.x;
    int l0 = c * CHL;
    float A = 1.f, Hl = 0.f;
#pragma unroll 4
    for (int t = 0; t < CHL; t++) {
        size_t idx = (size_t)(bb * LLEN + l0 + t) * HID + hh * 64 + d;
        float av = a[idx], bv = b[idx];
        Hl = fmaf(av, Hl, bv);
        A *= av;
        hout[idx] = Hl;
        apre[idx] = A;
    }
    int ai = (bh * NCHK + c) * 64 + d;
    aggA[ai] = A;
    aggH[ai] = Hl;
}

__global__ void scan2_k(const float* __restrict__ aggA, const float* __restrict__ aggH,
                        float* __restrict__ carry)
{
    int bh = blockIdx.x;
    int d = threadIdx.x;
    float c = 0.f;
#pragma unroll
    for (int ch = 0; ch < NCHK; ch++) {
        int ai = (bh * NCHK + ch) * 64 + d;
        carry[ai] = c;
        c = fmaf(aggA[ai], c, aggH[ai]);
    }
}

// ------------------- per-head GEMM with fused scan fixup ----------------------
// z = ((h + carry*ap) @ WC[h] + bC[h]) * d
__global__ void __launch_bounds__(256)
head_k(const float* __restrict__ hmat, const float* __restrict__ apre,
       const float* __restrict__ carry,
       const float* __restrict__ WC, const float* __restrict__ bC,
       const float* __restrict__ dg, float* __restrict__ z)
{
    __shared__ float Ws[64][65];
    __shared__ float Hs[64][129];
    int hh = blockIdx.y;
    int r0 = blockIdx.x * 128;
    int tid = threadIdx.x;

    const float* wp = WC + (size_t)hh * 64 * 64;
    for (int id = tid; id < 1024; id += 256) {
        int k = id >> 4; int f = (id & 15) * 4;
        float4 v = *(const float4*)(wp + k * 64 + f);
        Ws[k][f] = v.x; Ws[k][f+1] = v.y; Ws[k][f+2] = v.z; Ws[k][f+3] = v.w;
    }
    for (int id = tid; id < 2048; id += 256) {
        int row = id >> 4; int d4 = (id & 15) * 4;
        int rg = r0 + row;
        size_t gi = (size_t)rg * HID + hh * 64 + d4;
        float4 v  = *(const float4*)(hmat + gi);
        float4 ap = *(const float4*)(apre + gi);
        int bb = rg >> 11, l = rg & (LLEN - 1), cc = l >> 6;
        int ai = (((bb * HH + hh) * NCHK) + cc) * 64 + d4;
        float4 cr = *(const float4*)(carry + ai);
        Hs[d4][row]   = fmaf(cr.x, ap.x, v.x);
        Hs[d4+1][row] = fmaf(cr.y, ap.y, v.y);
        Hs[d4+2][row] = fmaf(cr.z, ap.z, v.z);
        Hs[d4+3][row] = fmaf(cr.w, ap.w, v.w);
    }
    __syncthreads();

    int tx = tid & 15, ty = tid >> 4;
    float acc[8][4];
#pragma unroll
    for (int i = 0; i < 8; i++)
#pragma unroll
        for (int j = 0; j < 4; j++) acc[i][j] = 0.f;

#pragma unroll 8
    for (int k = 0; k < 64; k++) {
        float ar[8], br[4];
#pragma unroll
        for (int i = 0; i < 8; i++) ar[i] = Hs[k][ty * 8 + i];
#pragma unroll
        for (int j = 0; j < 4; j++) br[j] = Ws[k][tx * 4 + j];
#pragma unroll
        for (int i = 0; i < 8; i++)
#pragma unroll
            for (int j = 0; j < 4; j++)
                acc[i][j] = fmaf(ar[i], br[j], acc[i][j]);
    }
#pragma unroll
    for (int i = 0; i < 8; i++) {
        int row = r0 + ty * 8 + i;
#pragma unroll
        for (int j = 0; j < 4; j++) {
            int f = tx * 4 + j;
            size_t idx = (size_t)row * HID + hh * 64 + f;
            z[idx] = (acc[i][j] + bC[hh * 64 + f]) * dg[idx];
        }
    }
}

// ------------------- layernorm: u = z + LN(z), emits fp32 + fp16 -------------
__device__ __forceinline__ float warp_sum(float v) {
#pragma unroll
    for (int o = 16; o > 0; o >>= 1) v += __shfl_xor_sync(0xffffffffu, v, o);
    return v;
}

__global__ void __launch_bounds__(256)
ln2_k(const float* __restrict__ z, const float* __restrict__ g,
      const float* __restrict__ be, float* __restrict__ u, __half* __restrict__ uh)
{
    __shared__ float red[8];
    int row = blockIdx.x;
    int tid = threadIdx.x;
    const float* zr = z + (size_t)row * HID;
    float4 v = *(const float4*)(zr + tid * 4);

    float s = v.x + v.y + v.z + v.w;
    s = warp_sum(s);
    if ((tid & 31) == 0) red[tid >> 5] = s;
    __syncthreads();
    float tot = 0.f;
#pragma unroll
    for (int i = 0; i < 8; i++) tot += red[i];
    float mu = tot * (1.0f / HID);
    __syncthreads();

    float dx0 = v.x - mu, dx1 = v.y - mu, dx2 = v.z - mu, dx3 = v.w - mu;
    float ss = dx0*dx0 + dx1*dx1 + dx2*dx2 + dx3*dx3;
    ss = warp_sum(ss);
    if ((tid & 31) == 0) red[tid >> 5] = ss;
    __syncthreads();
    float tot2 = 0.f;
#pragma unroll
    for (int i = 0; i < 8; i++) tot2 += red[i];
    float rstd = rsqrtf(tot2 * (1.0f / HID) + EPSV);

    float4 gv = *(const float4*)(g + tid * 4);
    float4 bv = *(const float4*)(be + tid * 4);
    float4 o;
    o.x = v.x + dx0 * rstd * gv.x + bv.x;
    o.y = v.y + dx1 * rstd * gv.y + bv.y;
    o.z = v.z + dx2 * rstd * gv.z + bv.z;
    o.w = v.w + dx3 * rstd * gv.w + bv.w;
    *(float4*)(u + (size_t)row * HID + tid * 4) = o;
    *(uint2*)(uh + (size_t)row * HID + tid * 4) =
        make_uint2(pack2h(o.x, o.y), pack2h(o.z, o.w));
}

// ------------------- launch -------------------------------------------------
extern "C" void kernel_launch(void* const* d_in, const int* in_sizes, int n_in,
                              void* d_out, int out_size)
{
    const float* emb    = (const float*)d_in[0];
    const float* Wa     = (const float*)d_in[1];
    const float* ba     = (const float*)d_in[2];
    const float* Wb     = (const float*)d_in[3];
    const float* bb     = (const float*)d_in[4];
    const float* WD     = (const float*)d_in[5];
    const float* bD     = (const float*)d_in[6];
    const float* WC     = (const float*)d_in[7];
    const float* bC     = (const float*)d_in[8];
    const float* ffn1_w = (const float*)d_in[9];
    const float* ffn1_b = (const float*)d_in[10];
    const float* ffn2_w = (const float*)d_in[11];
    const float* ffn2_b = (const float*)d_in[12];
    const float* proj_w = (const float*)d_in[13];
    const float* proj_b = (const float*)d_in[14];
    const float* ln_g   = (const float*)d_in[15];
    const float* ln_b   = (const float*)d_in[16];
    float* out = (float*)d_out;

    float *pa, *pb, *pd, *ph, *pap, *pz, *pu, *paggA, *paggH, *pcarry, *pbcat;
    cudaGetSymbolAddress((void**)&pa, g_a);       cudaGetSymbolAddress((void**)&pb, g_b);
    cudaGetSymbolAddress((void**)&pd, g_d);       cudaGetSymbolAddress((void**)&ph, g_h);
    cudaGetSymbolAddress((void**)&pap, g_ap);     cudaGetSymbolAddress((void**)&pz, g_z);
    cudaGetSymbolAddress((void**)&pu, g_u);       cudaGetSymbolAddress((void**)&pbcat, g_bcat);
    cudaGetSymbolAddress((void**)&paggA, g_aggA); cudaGetSymbolAddress((void**)&paggH, g_aggH);
    cudaGetSymbolAddress((void**)&pcarry, g_carry);

    __half *pe, *puh, *pm, *pv;
    __half *wabdhi, *wabdlo, *f1hi, *f2hi, *pjhi;
    cudaGetSymbolAddress((void**)&pe, g_e);      cudaGetSymbolAddress((void**)&puh, g_uh);
    cudaGetSymbolAddress((void**)&pm, g_m);      cudaGetSymbolAddress((void**)&pv, g_v);
    cudaGetSymbolAddress((void**)&wabdhi, g_wabdhi);
    cudaGetSymbolAddress((void**)&wabdlo, g_wabdlo);
    cudaGetSymbolAddress((void**)&f1hi, g_f1hi); cudaGetSymbolAddress((void**)&f2hi, g_f2hi);
    cudaGetSymbolAddress((void**)&pjhi, g_pjhi);

    const int SM_C1 = 3 * 3 * 128 * 80;    // COMP=1, CK=32: 92160
    const int SM_C0 = 3 * 2 * 128 * 144;   // COMP=0, CK=64: 110592
    cudaFuncSetAttribute((const void*)hgemm<1,0,0,1,32>, cudaFuncAttributeMaxDynamicSharedMemorySize, SM_C1);
    cudaFuncSetAttribute((const void*)hgemm<3,0,0,0,64>, cudaFuncAttributeMaxDynamicSharedMemorySize, SM_C0);
    cudaFuncSetAttribute((const void*)hgemm<2,0,1,0,64>, cudaFuncAttributeMaxDynamicSharedMemorySize, SM_C0);
    cudaFuncSetAttribute((const void*)hgemm<0,1,1,0,64>, cudaFuncAttributeMaxDynamicSharedMemorySize, SM_C0);
    cudaFuncSetAttribute((const void*)hgemm<0,0,0,0,64>, cudaFuncAttributeMaxDynamicSharedMemorySize, SM_C0);

    // ---- prep ----
    tohalf_k<<<(ROWS * HID / 4 + 255) / 256, 256>>>(emb, pe, ROWS * HID / 4);            // 0
    convT3_k<<<dim3(HID/32, HID/32, 3), dim3(32,8)>>>(Wa, Wb, WD, wabdhi, wabdlo);        // 1
    bias3_k<<<(3*HID + 255)/256, 256>>>(ba, bb, bD, pbcat);                               // 2

    // a = tanh(emb@Wa + ba)  (compensated, CK=32)                             // 3 (ncu slot)
    hgemm<1,0,0,1,32><<<dim3(HID/128, ROWS/128), 256, SM_C1>>>(
        pe, wabdhi, wabdlo, ba, nullptr, pa, nullptr, nullptr, ROWS, HID, HID);
    // b|d = emb @ [Wb|WD] + [bb|bD]  (uncompensated, CK=64, sectioned out)
    hgemm<3,0,0,0,64><<<dim3(2*HID/128, ROWS/128), 256, SM_C0>>>(
        pe, wabdhi + (size_t)HID*HID, nullptr, pbcat + HID, nullptr, pb, nullptr, pd, ROWS, 2*HID, HID);

    // remaining weight prep (overlaps with scan path)
    convT_k<<<dim3(HID/32, FF/32),  dim3(32,8)>>>(ffn1_w, f1hi, nullptr, HID, FF);
    convT_k<<<dim3(FF/32,  HID/32), dim3(32,8)>>>(ffn2_w, f2hi, nullptr, FF, HID);
    convT_k<<<dim3(HID/32, HID/32), dim3(32,8)>>>(proj_w, pjhi, nullptr, HID, HID);

    // affine scan (chunk-local + cross-chunk carries; fixup fused into head_k)
    scan1_k<<<BBAT * HH * NCHK, 64>>>(pa, pb, ph, pap, paggA, paggH);
    scan2_k<<<BBAT * HH, 64>>>(paggA, paggH, pcarry);

    // z = ((h + carry*ap) @ WC + bC) * d
    head_k<<<dim3(ROWS / 128, HH), 256>>>(ph, pap, pcarry, WC, bC, pd, pz);

    // u = z + LN(z); emit u fp32 + fp16
    ln2_k<<<ROWS, 256>>>(pz, ln_g, ln_b, pu, puh);

    // mid = gelu(u@W1 + b1) -> fp16  (uncompensated, CK=64)
    hgemm<2,0,1,0,64><<<dim3(FF/128, ROWS/128), 256, SM_C0>>>(
        puh, f1hi, nullptr, ffn1_b, nullptr, nullptr, pm, nullptr, ROWS, FF, HID);
    // v = mid@W2 + b2 + u -> fp16  (uncompensated, CK=64)
    hgemm<0,1,1,0,64><<<dim3(HID/128, ROWS/128), 256, SM_C0>>>(
        pm, f2hi, nullptr, ffn2_b, pu, nullptr, pv, nullptr, ROWS, HID, FF);
    // out = v@proj + proj_b  (uncompensated, CK=64)
    hgemm<0,0,0,0,64><<<dim3(HID/128, ROWS/128), 256, SM_C0>>>(
        pv, pjhi, nullptr, proj_b, nullptr, out, nullptr, nullptr, ROWS, HID, HID);
}